// round 1
// baseline (speedup 1.0000x reference)
#include <cuda_runtime.h>
#include <cuda_bf16.h>
#include <cstdint>

// Problem constants (max sizes for static scratch)
#define MAXN 50000
#define D_IN 128
#define D_OUT 128
#define DCAT 396      // 3*128 + 2*6
#define D_NODEREP 134 // 128 + 6
#define DH 256
#define TILE_E 32
#define EPS 1e-5f

// Scratch (static device globals: no allocation allowed)
__device__ float g_agg[(size_t)MAXN * D_IN];
__device__ float g_den[MAXN];

// ---------------------------------------------------------------------------
// Kernel 1: zero the scratch
// ---------------------------------------------------------------------------
__global__ void zero_kernel(int N) {
    int idx = blockIdx.x * blockDim.x + threadIdx.x;
    int total = N * D_IN;
    if (idx < total) g_agg[idx] = 0.f;
    if (idx < N) g_den[idx] = 0.f;
}

// ---------------------------------------------------------------------------
// Kernel 2: masked scatter-add aggregation (warp per edge)
// ---------------------------------------------------------------------------
__global__ void agg_kernel(const float* __restrict__ edge_attr,
                           const float* __restrict__ mask,
                           const int* __restrict__ edge_index, int E) {
    int w = (blockIdx.x * blockDim.x + threadIdx.x) >> 5;
    int lane = threadIdx.x & 31;
    if (w >= E) return;
    float m = mask[w];
    if (m == 0.f) return;  // ~50% of edges skip entirely
    int col = edge_index[E + w];
    const float* a = edge_attr + (size_t)w * D_IN;
    float* dst = g_agg + (size_t)col * D_IN;
#pragma unroll
    for (int q = 0; q < 4; q++) {
        int c = lane + 32 * q;
        atomicAdd(dst + c, a[c] * m);
    }
    if (lane == 0) atomicAdd(g_den + col, m);
}

// ---------------------------------------------------------------------------
// Kernel 3: node_rep = concat(agg/den, x)  -> written straight into d_out
// ---------------------------------------------------------------------------
__global__ void noderep_kernel(const float* __restrict__ x,
                               float* __restrict__ out_node, int N) {
    int idx = blockIdx.x * blockDim.x + threadIdx.x;
    int total = N * D_NODEREP;
    if (idx >= total) return;
    int n = idx / D_NODEREP;
    int c = idx - n * D_NODEREP;
    float v;
    if (c < D_IN)
        v = g_agg[(size_t)n * D_IN + c] / (g_den[n] + 1.0f);
    else
        v = x[n * 6 + (c - D_IN)];
    out_node[idx] = v;
}

// ---------------------------------------------------------------------------
// Kernel 4: fused per-edge MLP.
// 32 edges / block, 128 threads. tx = lane, ty = warp.
// Each warp owns 8 edges end-to-end after the gather barrier.
// Thread (ty,tx): GEMM1/3 tile = 8 edges x 4 cols, GEMM2 tile = 8 x 8.
// ---------------------------------------------------------------------------
__global__ void __launch_bounds__(128)
edge_kernel(const float* __restrict__ node_rep,
            const float* __restrict__ edge_attr,
            const int* __restrict__ edge_index,
            const float* __restrict__ We, const float* __restrict__ bE,
            const float* __restrict__ W1, const float* __restrict__ b1,
            const float* __restrict__ W2, const float* __restrict__ b2,
            const float* __restrict__ g1, const float* __restrict__ be1,
            const float* __restrict__ g2, const float* __restrict__ be2,
            float* __restrict__ out, int E) {
    extern __shared__ float sm[];
    float* feat = sm;                       // [32][396]
    float* hs = feat + TILE_E * DCAT;       // [32][128]
    float* ts = hs + TILE_E * D_OUT;        // [32][256]
    __shared__ int rows_s[TILE_E], cols_s[TILE_E];

    const int tid = threadIdx.x;
    const int e0 = blockIdx.x * TILE_E;

    if (tid < TILE_E) {
        int eg = e0 + tid;
        rows_s[tid] = (eg < E) ? edge_index[eg] : 0;
        cols_s[tid] = (eg < E) ? edge_index[E + eg] : 0;
    }
    __syncthreads();

    // Gather edge_rep = [node_rep[row] | node_rep[col] | edge_attr]
    for (int idx = tid; idx < TILE_E * DCAT; idx += 128) {
        int e = idx / DCAT;
        int k = idx - e * DCAT;
        int eg = e0 + e;
        float v = 0.f;
        if (eg < E) {
            if (k < D_NODEREP)
                v = node_rep[(size_t)rows_s[e] * D_NODEREP + k];
            else if (k < 2 * D_NODEREP)
                v = node_rep[(size_t)cols_s[e] * D_NODEREP + (k - D_NODEREP)];
            else
                v = edge_attr[(size_t)eg * D_IN + (k - 2 * D_NODEREP)];
        }
        feat[idx] = v;
    }
    __syncthreads();

    const int tx = tid & 31;
    const int ty = tid >> 5;

    // ---------------- GEMM1: [32,396] @ [396,128] ----------------
    float acc[8][4];
#pragma unroll
    for (int e = 0; e < 8; e++)
#pragma unroll
        for (int q = 0; q < 4; q++) acc[e][q] = 0.f;

    for (int k = 0; k < DCAT; k++) {
        const float* wr = We + (size_t)k * D_OUT + tx;
        float w0 = __ldg(wr), w1 = __ldg(wr + 32), w2 = __ldg(wr + 64), w3 = __ldg(wr + 96);
#pragma unroll
        for (int e = 0; e < 8; e++) {
            float f = feat[(ty * 8 + e) * DCAT + k];
            acc[e][0] = fmaf(f, w0, acc[e][0]);
            acc[e][1] = fmaf(f, w1, acc[e][1]);
            acc[e][2] = fmaf(f, w2, acc[e][2]);
            acc[e][3] = fmaf(f, w3, acc[e][3]);
        }
    }

    // residual + bias + LayerNorm1 -> hs
    float g1r[4], be1r[4], bEr[4];
#pragma unroll
    for (int q = 0; q < 4; q++) {
        g1r[q] = g1[tx + 32 * q];
        be1r[q] = be1[tx + 32 * q];
        bEr[q] = bE[tx + 32 * q];
    }
#pragma unroll
    for (int e = 0; e < 8; e++) {
        int el = ty * 8 + e;
#pragma unroll
        for (int q = 0; q < 4; q++)
            acc[e][q] += bEr[q] + feat[el * DCAT + 2 * D_NODEREP + tx + 32 * q];
        float s = 0.f, s2 = 0.f;
#pragma unroll
        for (int q = 0; q < 4; q++) { s += acc[e][q]; s2 += acc[e][q] * acc[e][q]; }
#pragma unroll
        for (int off = 16; off > 0; off >>= 1) {
            s += __shfl_xor_sync(0xFFFFFFFF, s, off);
            s2 += __shfl_xor_sync(0xFFFFFFFF, s2, off);
        }
        float mu = s * (1.f / 128.f);
        float var = s2 * (1.f / 128.f) - mu * mu;
        float r = rsqrtf(var + EPS);
#pragma unroll
        for (int q = 0; q < 4; q++)
            hs[el * D_OUT + tx + 32 * q] = (acc[e][q] - mu) * r * g1r[q] + be1r[q];
    }
    __syncwarp();

    // ---------------- GEMM2: relu(h @ W1 + b1) -> ts [32,256] ----------------
    float a2[8][8];
#pragma unroll
    for (int e = 0; e < 8; e++)
#pragma unroll
        for (int q = 0; q < 8; q++) a2[e][q] = 0.f;

    for (int k = 0; k < D_OUT; k++) {
        const float* wr = W1 + (size_t)k * DH + tx;
        float w[8];
#pragma unroll
        for (int q = 0; q < 8; q++) w[q] = __ldg(wr + 32 * q);
#pragma unroll
        for (int e = 0; e < 8; e++) {
            float f = hs[(ty * 8 + e) * D_OUT + k];
#pragma unroll
            for (int q = 0; q < 8; q++) a2[e][q] = fmaf(f, w[q], a2[e][q]);
        }
    }
    {
        float b1r[8];
#pragma unroll
        for (int q = 0; q < 8; q++) b1r[q] = b1[tx + 32 * q];
#pragma unroll
        for (int e = 0; e < 8; e++) {
            int el = ty * 8 + e;
#pragma unroll
            for (int q = 0; q < 8; q++)
                ts[el * DH + tx + 32 * q] = fmaxf(a2[e][q] + b1r[q], 0.f);
        }
    }
    __syncwarp();

    // ---------------- GEMM3: t @ W2, +h +b2, LayerNorm2 -> out ----------------
    float a3[8][4];
#pragma unroll
    for (int e = 0; e < 8; e++)
#pragma unroll
        for (int q = 0; q < 4; q++) a3[e][q] = 0.f;

    for (int k = 0; k < DH; k++) {
        const float* wr = W2 + (size_t)k * D_OUT + tx;
        float w0 = __ldg(wr), w1 = __ldg(wr + 32), w2 = __ldg(wr + 64), w3 = __ldg(wr + 96);
#pragma unroll
        for (int e = 0; e < 8; e++) {
            float f = ts[(ty * 8 + e) * DH + k];
            a3[e][0] = fmaf(f, w0, a3[e][0]);
            a3[e][1] = fmaf(f, w1, a3[e][1]);
            a3[e][2] = fmaf(f, w2, a3[e][2]);
            a3[e][3] = fmaf(f, w3, a3[e][3]);
        }
    }

    float g2r[4], be2r[4], b2r[4];
#pragma unroll
    for (int q = 0; q < 4; q++) {
        g2r[q] = g2[tx + 32 * q];
        be2r[q] = be2[tx + 32 * q];
        b2r[q] = b2[tx + 32 * q];
    }
#pragma unroll
    for (int e = 0; e < 8; e++) {
        int el = ty * 8 + e;
        int eg = e0 + el;
        float z[4];
#pragma unroll
        for (int q = 0; q < 4; q++)
            z[q] = hs[el * D_OUT + tx + 32 * q] + a3[e][q] + b2r[q];
        float s = 0.f, s2 = 0.f;
#pragma unroll
        for (int q = 0; q < 4; q++) { s += z[q]; s2 += z[q] * z[q]; }
#pragma unroll
        for (int off = 16; off > 0; off >>= 1) {
            s += __shfl_xor_sync(0xFFFFFFFF, s, off);
            s2 += __shfl_xor_sync(0xFFFFFFFF, s2, off);
        }
        float mu = s * (1.f / 128.f);
        float var = s2 * (1.f / 128.f) - mu * mu;
        float r = rsqrtf(var + EPS);
        if (eg < E) {
#pragma unroll
            for (int q = 0; q < 4; q++)
                out[(size_t)eg * D_OUT + tx + 32 * q] = (z[q] - mu) * r * g2r[q] + be2r[q];
        }
    }
}

// ---------------------------------------------------------------------------
// launch
// ---------------------------------------------------------------------------
extern "C" void kernel_launch(void* const* d_in, const int* in_sizes, int n_in,
                              void* d_out, int out_size) {
    // Bind inputs in dict order, skipping scalar (size-1) entries like num_nodes.
    const void* p[16];
    int sz[16];
    int m = 0;
    for (int i = 0; i < n_in && m < 16; i++) {
        if (in_sizes[i] == 1) continue;
        p[m] = d_in[i];
        sz[m] = in_sizes[i];
        m++;
    }
    const float* x         = (const float*)p[0];
    const int*   edge_index = (const int*)p[1];
    const float* edge_attr = (const float*)p[2];
    const float* mask      = (const float*)p[3];
    const float* We        = (const float*)p[4];
    const float* bE        = (const float*)p[5];
    const float* W1        = (const float*)p[6];
    const float* b1        = (const float*)p[7];
    const float* W2        = (const float*)p[8];
    const float* b2        = (const float*)p[9];
    const float* g1        = (const float*)p[10];
    const float* be1       = (const float*)p[11];
    const float* g2        = (const float*)p[12];
    const float* be2       = (const float*)p[13];

    const int N = sz[0] / 6;
    const int E = sz[3];

    float* out_node = (float*)d_out;                      // [N,134]
    float* out_edge = out_node + (size_t)N * D_NODEREP;   // [E,128]

    // 1) zero scratch
    {
        int total = N * D_IN;
        int blocks = (total + 255) / 256;
        zero_kernel<<<blocks, 256>>>(N);
    }
    // 2) aggregation (warp per edge, 8 warps/block)
    {
        int blocks = (E + 7) / 8;
        agg_kernel<<<blocks, 256>>>(edge_attr, mask, edge_index, E);
    }
    // 3) node_rep
    {
        int total = N * D_NODEREP;
        int blocks = (total + 255) / 256;
        noderep_kernel<<<blocks, 256>>>(x, out_node, N);
    }
    // 4) fused edge MLP
    {
        const int smem = (TILE_E * DCAT + TILE_E * D_OUT + TILE_E * DH) * (int)sizeof(float);
        cudaFuncSetAttribute(edge_kernel, cudaFuncAttributeMaxDynamicSharedMemorySize, smem);
        int blocks = (E + TILE_E - 1) / TILE_E;
        edge_kernel<<<blocks, 128, smem>>>(out_node, edge_attr, edge_index,
                                           We, bE, W1, b1, W2, b2,
                                           g1, be1, g2, be2, out_edge, E);
    }
}

// round 2
// speedup vs baseline: 2.3712x; 2.3712x over previous
#include <cuda_runtime.h>
#include <cuda_bf16.h>
#include <cstdint>

// ---------------------------------------------------------------------------
// Problem constants
// ---------------------------------------------------------------------------
#define MAXN 50000
#define D_IN 128
#define D_OUT 128
#define DCAT 396       // 3*128 + 2*6
#define D_NODEREP 134  // 128 + 6
#define DH 256
#define EPS 1e-5f

#define TILE_E 64
#define THREADS 256
#define KPAD 416       // DCAT padded to multiple of 32

// smem strides (floats) — chosen for conflict-free mma fragment LDS
#define S_FEAT 420     // mod 32 = 4
#define S_H 132        // mod 32 = 4
#define S_T 260        // mod 32 = 4
#define S_WA 136       // 128-col weight chunks, mod 32 = 8
#define S_WB 264       // 256-col weight chunks, mod 32 = 8

// smem layout (floats)
#define FEAT_OFF 0
#define FEAT_FLOATS (TILE_E * S_FEAT)          // 26880
#define H_OFF FEAT_FLOATS                      // 26880
#define H_FLOATS (TILE_E * S_H)                // 8448
#define WB_OFF (H_OFF + H_FLOATS)              // 35328
#define WB_BUF 4352                            // max(32*136, 16*264)
#define SMEM_FLOATS (WB_OFF + 2 * WB_BUF)      // 44032
#define T_OFF 0                                // overlays feat (dead after G1)
#define Z_OFF (TILE_E * S_T)                   // 16640, inside feat region

// Scratch (static device globals: no allocation allowed)
__device__ float g_agg[(size_t)MAXN * D_IN];
__device__ float g_den[MAXN];

// ---------------------------------------------------------------------------
// helpers
// ---------------------------------------------------------------------------
__device__ __forceinline__ unsigned f2tf(float f) {
    unsigned u;
    asm("cvt.rna.tf32.f32 %0, %1;" : "=r"(u) : "f"(f));
    return u;
}

__device__ __forceinline__ void mma_tf32(float* c, const unsigned* a,
                                         unsigned b0, unsigned b1) {
    asm volatile(
        "mma.sync.aligned.m16n8k8.row.col.f32.tf32.tf32.f32 "
        "{%0,%1,%2,%3},{%4,%5,%6,%7},{%8,%9},{%0,%1,%2,%3};\n"
        : "+f"(c[0]), "+f"(c[1]), "+f"(c[2]), "+f"(c[3])
        : "r"(a[0]), "r"(a[1]), "r"(a[2]), "r"(a[3]), "r"(b0), "r"(b1));
}

// ---------------------------------------------------------------------------
// Kernel 1: zero the scratch
// ---------------------------------------------------------------------------
__global__ void zero_kernel(int N) {
    int idx = blockIdx.x * blockDim.x + threadIdx.x;
    int total = N * D_IN;
    if (idx < total) g_agg[idx] = 0.f;
    if (idx < N) g_den[idx] = 0.f;
}

// ---------------------------------------------------------------------------
// Kernel 2: masked scatter-add aggregation (warp per edge, float4 atomics)
// ---------------------------------------------------------------------------
__global__ void agg_kernel(const float* __restrict__ edge_attr,
                           const float* __restrict__ mask,
                           const int* __restrict__ edge_index, int E) {
    int w = (blockIdx.x * blockDim.x + threadIdx.x) >> 5;
    int lane = threadIdx.x & 31;
    if (w >= E) return;
    float m = mask[w];
    if (m == 0.f) return;
    int col = edge_index[E + w];
    const float4* a = (const float4*)(edge_attr + (size_t)w * D_IN);
    float4* dst = (float4*)(g_agg + (size_t)col * D_IN);
    float4 v = a[lane];
    v.x *= m; v.y *= m; v.z *= m; v.w *= m;
    atomicAdd(dst + lane, v);
    if (lane == 0) atomicAdd(g_den + col, m);
}

// ---------------------------------------------------------------------------
// Kernel 3: node_rep = concat(agg/den, x)  -> written straight into d_out
// ---------------------------------------------------------------------------
__global__ void noderep_kernel(const float* __restrict__ x,
                               float* __restrict__ out_node, int N) {
    int idx = blockIdx.x * blockDim.x + threadIdx.x;
    int total = N * D_NODEREP;
    if (idx >= total) return;
    int n = idx / D_NODEREP;
    int c = idx - n * D_NODEREP;
    float v;
    if (c < D_IN)
        v = g_agg[(size_t)n * D_IN + c] / (g_den[n] + 1.0f);
    else
        v = x[n * 6 + (c - D_IN)];
    out_node[idx] = v;
}

// ---------------------------------------------------------------------------
// Kernel 4: fused per-edge MLP on tensor cores (tf32 mma.sync).
// 64 edges / block, 256 threads (8 warps: wm = wid>>2 in {0,1}, wn = wid&3).
// ---------------------------------------------------------------------------
__global__ void __launch_bounds__(THREADS, 1)
edge_kernel(const float* __restrict__ node_rep,
            const float* __restrict__ edge_attr,
            const int* __restrict__ edge_index,
            const float* __restrict__ We, const float* __restrict__ bE,
            const float* __restrict__ W1, const float* __restrict__ b1,
            const float* __restrict__ W2, const float* __restrict__ b2,
            const float* __restrict__ g1, const float* __restrict__ be1,
            const float* __restrict__ g2, const float* __restrict__ be2,
            float* __restrict__ out, int E) {
    extern __shared__ float sm[];
    float* feat = sm + FEAT_OFF;
    float* hbuf = sm + H_OFF;
    float* wb = sm + WB_OFF;
    float* tbuf = sm + T_OFF;
    float* zbuf = sm + Z_OFF;
    __shared__ int rows_s[TILE_E], cols_s[TILE_E];

    const int tid = threadIdx.x;
    const int lane = tid & 31;
    const int wid = tid >> 5;
    const int e0 = blockIdx.x * TILE_E;

    const int m0 = 32 * (wid >> 2);   // warp row base (0 or 32)
    const int wn = wid & 3;
    const int r0 = lane >> 2;         // fragment row within 8
    const int qk = lane & 3;          // fragment k/col within 4
    const int cb = 2 * qk;            // accum column base

    if (tid < TILE_E) {
        int eg = e0 + tid;
        rows_s[tid] = (eg < E) ? edge_index[eg] : 0;
        cols_s[tid] = (eg < E) ? edge_index[E + eg] : 0;
    }
    __syncthreads();

    // ---- stage weight chunk 0 for GEMM1 + gather feat ----
    {
        float* dst = wb;  // buffer 0
#pragma unroll
        for (int ii = 0; ii < 16; ii++) {
            int i = tid + ii * THREADS;
            int r = i >> 7, c = i & 127;
            float w = (r < DCAT) ? __ldg(&We[r * D_OUT + c]) : 0.f;
            dst[r * S_WA + c] = __uint_as_float(f2tf(w));
        }
    }
    for (int idx = tid; idx < TILE_E * KPAD; idx += THREADS) {
        int e = idx / KPAD;
        int k = idx - e * KPAD;
        int eg = e0 + e;
        float v = 0.f;
        if (eg < E && k < DCAT) {
            if (k < D_NODEREP)
                v = node_rep[(size_t)rows_s[e] * D_NODEREP + k];
            else if (k < 2 * D_NODEREP)
                v = node_rep[(size_t)cols_s[e] * D_NODEREP + (k - D_NODEREP)];
            else
                v = edge_attr[(size_t)eg * D_IN + (k - 2 * D_NODEREP)];
        }
        feat[e * S_FEAT + k] = v;
    }
    __syncthreads();

    // ================= GEMM1: feat[64,416] @ We[416,128] =================
    // warp tile: m32 x n32 (mt 0..1, nt 0..3), 13 chunks of 32 k-rows
    {
        const int n0 = 32 * wn;
        float acc[2][4][4];
#pragma unroll
        for (int mt = 0; mt < 2; mt++)
#pragma unroll
            for (int nt = 0; nt < 4; nt++)
#pragma unroll
                for (int q = 0; q < 4; q++) acc[mt][nt][q] = 0.f;

        const int NCH = KPAD / 32;  // 13
        for (int ch = 0; ch < NCH; ch++) {
            float* cur = wb + (ch & 1) * WB_BUF;
            if (ch + 1 < NCH) {
                float* nxt = wb + ((ch + 1) & 1) * WB_BUF;
                int kb = (ch + 1) * 32;
#pragma unroll
                for (int ii = 0; ii < 16; ii++) {
                    int i = tid + ii * THREADS;
                    int r = i >> 7, c = i & 127;
                    int k = kb + r;
                    float w = (k < DCAT) ? __ldg(&We[k * D_OUT + c]) : 0.f;
                    nxt[r * S_WA + c] = __uint_as_float(f2tf(w));
                }
            }
#pragma unroll
            for (int ks = 0; ks < 4; ks++) {
                int k0 = ch * 32 + ks * 8;
                unsigned a[2][4];
#pragma unroll
                for (int mt = 0; mt < 2; mt++) {
                    const float* ap = feat + (m0 + 16 * mt + r0) * S_FEAT + k0 + qk;
                    a[mt][0] = f2tf(ap[0]);
                    a[mt][1] = f2tf(ap[8 * S_FEAT]);
                    a[mt][2] = f2tf(ap[4]);
                    a[mt][3] = f2tf(ap[8 * S_FEAT + 4]);
                }
#pragma unroll
                for (int nt = 0; nt < 4; nt++) {
                    const float* bp = cur + (ks * 8 + qk) * S_WA + n0 + 8 * nt + r0;
                    unsigned b0 = __float_as_uint(bp[0]);
                    unsigned b1 = __float_as_uint(bp[4 * S_WA]);
                    mma_tf32(acc[0][nt], a[0], b0, b1);
                    mma_tf32(acc[1][nt], a[1], b0, b1);
                }
            }
            __syncthreads();
        }

        // write raw h = acc + bE + edge_attr residual (feat cols 268..395)
#pragma unroll
        for (int mt = 0; mt < 2; mt++)
#pragma unroll
            for (int nt = 0; nt < 4; nt++) {
                int row = m0 + 16 * mt + r0;
                int col = n0 + 8 * nt + cb;
#pragma unroll
                for (int q = 0; q < 4; q++) {
                    int rr = row + (q >> 1) * 8;
                    int cc = col + (q & 1);
                    hbuf[rr * S_H + cc] =
                        acc[mt][nt][q] + __ldg(&bE[cc]) + feat[rr * S_FEAT + 2 * D_NODEREP + cc];
                }
            }
    }
    __syncthreads();

    // ---------------- LayerNorm1 (in place on hbuf) ----------------
    for (int r = wid; r < TILE_E; r += 8) {
        float v[4], s = 0.f, s2 = 0.f;
#pragma unroll
        for (int q = 0; q < 4; q++) {
            v[q] = hbuf[r * S_H + lane + 32 * q];
            s += v[q];
            s2 += v[q] * v[q];
        }
#pragma unroll
        for (int off = 16; off > 0; off >>= 1) {
            s += __shfl_xor_sync(0xFFFFFFFF, s, off);
            s2 += __shfl_xor_sync(0xFFFFFFFF, s2, off);
        }
        float mu = s * (1.f / 128.f);
        float var = s2 * (1.f / 128.f) - mu * mu;
        float rinv = rsqrtf(var + EPS);
#pragma unroll
        for (int q = 0; q < 4; q++) {
            int c = lane + 32 * q;
            hbuf[r * S_H + c] = (v[q] - mu) * rinv * __ldg(&g1[c]) + __ldg(&be1[c]);
        }
    }
    __syncthreads();

    // ================= GEMM2: h[64,128] @ W1[128,256], relu -> t ==========
    // warp tile m32 x n64 (nt 0..7), 8 chunks of 16 k-rows
    {
        const int n0 = 64 * wn;
        float acc[2][8][4];
#pragma unroll
        for (int mt = 0; mt < 2; mt++)
#pragma unroll
            for (int nt = 0; nt < 8; nt++)
#pragma unroll
                for (int q = 0; q < 4; q++) acc[mt][nt][q] = 0.f;

        // stage chunk 0
        {
            float* dst = wb;
#pragma unroll
            for (int ii = 0; ii < 16; ii++) {
                int i = tid + ii * THREADS;
                int r = i >> 8, c = i & 255;
                dst[r * S_WB + c] = __uint_as_float(f2tf(__ldg(&W1[r * DH + c])));
            }
        }
        __syncthreads();

        const int NCH = D_OUT / 16;  // 8
        for (int ch = 0; ch < NCH; ch++) {
            float* cur = wb + (ch & 1) * WB_BUF;
            if (ch + 1 < NCH) {
                float* nxt = wb + ((ch + 1) & 1) * WB_BUF;
                int kb = (ch + 1) * 16;
#pragma unroll
                for (int ii = 0; ii < 16; ii++) {
                    int i = tid + ii * THREADS;
                    int r = i >> 8, c = i & 255;
                    nxt[r * S_WB + c] = __uint_as_float(f2tf(__ldg(&W1[(kb + r) * DH + c])));
                }
            }
#pragma unroll
            for (int ks = 0; ks < 2; ks++) {
                int k0 = ch * 16 + ks * 8;
                unsigned a[2][4];
#pragma unroll
                for (int mt = 0; mt < 2; mt++) {
                    const float* ap = hbuf + (m0 + 16 * mt + r0) * S_H + k0 + qk;
                    a[mt][0] = f2tf(ap[0]);
                    a[mt][1] = f2tf(ap[8 * S_H]);
                    a[mt][2] = f2tf(ap[4]);
                    a[mt][3] = f2tf(ap[8 * S_H + 4]);
                }
#pragma unroll
                for (int nt = 0; nt < 8; nt++) {
                    const float* bp = cur + (ks * 8 + qk) * S_WB + n0 + 8 * nt + r0;
                    unsigned b0 = __float_as_uint(bp[0]);
                    unsigned b1 = __float_as_uint(bp[4 * S_WB]);
                    mma_tf32(acc[0][nt], a[0], b0, b1);
                    mma_tf32(acc[1][nt], a[1], b0, b1);
                }
            }
            __syncthreads();
        }

        // t = relu(acc + b1), stored tf32-rounded (GEMM3 A operand only)
#pragma unroll
        for (int mt = 0; mt < 2; mt++)
#pragma unroll
            for (int nt = 0; nt < 8; nt++) {
                int row = m0 + 16 * mt + r0;
                int col = n0 + 8 * nt + cb;
#pragma unroll
                for (int q = 0; q < 4; q++) {
                    int rr = row + (q >> 1) * 8;
                    int cc = col + (q & 1);
                    float t = fmaxf(acc[mt][nt][q] + __ldg(&b1[cc]), 0.f);
                    tbuf[rr * S_T + cc] = __uint_as_float(f2tf(t));
                }
            }
    }
    __syncthreads();

    // ================= GEMM3: t[64,256] @ W2[256,128] ====================
    // warp tile m32 x n32, 8 chunks of 32 k-rows
    {
        const int n0 = 32 * wn;
        float acc[2][4][4];
#pragma unroll
        for (int mt = 0; mt < 2; mt++)
#pragma unroll
            for (int nt = 0; nt < 4; nt++)
#pragma unroll
                for (int q = 0; q < 4; q++) acc[mt][nt][q] = 0.f;

        // stage chunk 0
        {
            float* dst = wb;
#pragma unroll
            for (int ii = 0; ii < 16; ii++) {
                int i = tid + ii * THREADS;
                int r = i >> 7, c = i & 127;
                dst[r * S_WA + c] = __uint_as_float(f2tf(__ldg(&W2[r * D_OUT + c])));
            }
        }
        __syncthreads();

        const int NCH = DH / 32;  // 8
        for (int ch = 0; ch < NCH; ch++) {
            float* cur = wb + (ch & 1) * WB_BUF;
            if (ch + 1 < NCH) {
                float* nxt = wb + ((ch + 1) & 1) * WB_BUF;
                int kb = (ch + 1) * 32;
#pragma unroll
                for (int ii = 0; ii < 16; ii++) {
                    int i = tid + ii * THREADS;
                    int r = i >> 7, c = i & 127;
                    nxt[r * S_WA + c] = __uint_as_float(f2tf(__ldg(&W2[(kb + r) * D_OUT + c])));
                }
            }
#pragma unroll
            for (int ks = 0; ks < 4; ks++) {
                int k0 = ch * 32 + ks * 8;
                unsigned a[2][4];
#pragma unroll
                for (int mt = 0; mt < 2; mt++) {
                    const float* ap = tbuf + (m0 + 16 * mt + r0) * S_T + k0 + qk;
                    a[mt][0] = __float_as_uint(ap[0]);
                    a[mt][1] = __float_as_uint(ap[8 * S_T]);
                    a[mt][2] = __float_as_uint(ap[4]);
                    a[mt][3] = __float_as_uint(ap[8 * S_T + 4]);
                }
#pragma unroll
                for (int nt = 0; nt < 4; nt++) {
                    const float* bp = cur + (ks * 8 + qk) * S_WA + n0 + 8 * nt + r0;
                    unsigned b0 = __float_as_uint(bp[0]);
                    unsigned b1 = __float_as_uint(bp[4 * S_WA]);
                    mma_tf32(acc[0][nt], a[0], b0, b1);
                    mma_tf32(acc[1][nt], a[1], b0, b1);
                }
            }
            __syncthreads();
        }

        // z = acc + b2 + h (residual), to zbuf
#pragma unroll
        for (int mt = 0; mt < 2; mt++)
#pragma unroll
            for (int nt = 0; nt < 4; nt++) {
                int row = m0 + 16 * mt + r0;
                int col = n0 + 8 * nt + cb;
#pragma unroll
                for (int q = 0; q < 4; q++) {
                    int rr = row + (q >> 1) * 8;
                    int cc = col + (q & 1);
                    zbuf[rr * S_H + cc] =
                        acc[mt][nt][q] + __ldg(&b2[cc]) + hbuf[rr * S_H + cc];
                }
            }
    }
    __syncthreads();

    // ---------------- LayerNorm2 -> global out ----------------
    for (int r = wid; r < TILE_E; r += 8) {
        int eg = e0 + r;
        float v[4], s = 0.f, s2 = 0.f;
#pragma unroll
        for (int q = 0; q < 4; q++) {
            v[q] = zbuf[r * S_H + lane + 32 * q];
            s += v[q];
            s2 += v[q] * v[q];
        }
#pragma unroll
        for (int off = 16; off > 0; off >>= 1) {
            s += __shfl_xor_sync(0xFFFFFFFF, s, off);
            s2 += __shfl_xor_sync(0xFFFFFFFF, s2, off);
        }
        float mu = s * (1.f / 128.f);
        float var = s2 * (1.f / 128.f) - mu * mu;
        float rinv = rsqrtf(var + EPS);
        if (eg < E) {
#pragma unroll
            for (int q = 0; q < 4; q++) {
                int c = lane + 32 * q;
                out[(size_t)eg * D_OUT + c] = (v[q] - mu) * rinv * __ldg(&g2[c]) + __ldg(&be2[c]);
            }
        }
    }
}

// ---------------------------------------------------------------------------
// launch
// ---------------------------------------------------------------------------
extern "C" void kernel_launch(void* const* d_in, const int* in_sizes, int n_in,
                              void* d_out, int out_size) {
    const void* p[16];
    int sz[16];
    int m = 0;
    for (int i = 0; i < n_in && m < 16; i++) {
        if (in_sizes[i] == 1) continue;
        p[m] = d_in[i];
        sz[m] = in_sizes[i];
        m++;
    }
    const float* x          = (const float*)p[0];
    const int*   edge_index = (const int*)p[1];
    const float* edge_attr  = (const float*)p[2];
    const float* mask       = (const float*)p[3];
    const float* We         = (const float*)p[4];
    const float* bE         = (const float*)p[5];
    const float* W1         = (const float*)p[6];
    const float* b1         = (const float*)p[7];
    const float* W2         = (const float*)p[8];
    const float* b2         = (const float*)p[9];
    const float* g1         = (const float*)p[10];
    const float* be1        = (const float*)p[11];
    const float* g2         = (const float*)p[12];
    const float* be2        = (const float*)p[13];

    const int N = sz[0] / 6;
    const int E = sz[3];

    float* out_node = (float*)d_out;                     // [N,134]
    float* out_edge = out_node + (size_t)N * D_NODEREP;  // [E,128]

    {
        int total = N * D_IN;
        zero_kernel<<<(total + 255) / 256, 256>>>(N);
    }
    {
        agg_kernel<<<(E + 7) / 8, 256>>>(edge_attr, mask, edge_index, E);
    }
    {
        int total = N * D_NODEREP;
        noderep_kernel<<<(total + 255) / 256, 256>>>(x, out_node, N);
    }
    {
        const int smem = SMEM_FLOATS * (int)sizeof(float);
        cudaFuncSetAttribute(edge_kernel, cudaFuncAttributeMaxDynamicSharedMemorySize, smem);
        int blocks = (E + TILE_E - 1) / TILE_E;
        edge_kernel<<<blocks, THREADS, smem>>>(out_node, edge_attr, edge_index,
                                               We, bE, W1, b1, W2, b2,
                                               g1, be1, g2, be2, out_edge, E);
    }
}

// round 3
// speedup vs baseline: 3.6758x; 1.5502x over previous
#include <cuda_runtime.h>
#include <cuda_bf16.h>
#include <cstdint>

// ---------------------------------------------------------------------------
// Problem constants
// ---------------------------------------------------------------------------
#define MAXN 50000
#define D_IN 128
#define D_OUT 128
#define DCAT 396       // 3*128 + 2*6
#define D_NODEREP 134  // 128 + 6
#define DH 256
#define EPS 1e-5f

#define TILE_E 64
#define THREADS 512
#define KPAD 416       // DCAT padded to multiple of 32

// smem strides (floats) — conflict-free mma fragment LDS
#define S_FEAT 420     // mod 32 = 4
#define S_H 132        // mod 32 = 4
#define S_T 260        // mod 32 = 4
#define S_WA 136       // 128-col weight chunks, mod 32 = 8
#define S_WB 264       // 256-col weight chunks, mod 32 = 8

// smem layout (floats)
#define FEAT_OFF 0
#define FEAT_FLOATS (TILE_E * S_FEAT)          // 26880
#define H_OFF FEAT_FLOATS                      // 26880
#define H_FLOATS (TILE_E * S_H)                // 8448
#define WB_OFF (H_OFF + H_FLOATS)              // 35328
#define WB_BUF 4352                            // max(32*136, 16*264)
#define NSTAGE 3
#define SMEM_FLOATS (WB_OFF + NSTAGE * WB_BUF) // 48384 floats = 193.5 KB
#define T_OFF 0                                // overlays feat (dead after G1)
#define Z_OFF (TILE_E * S_T)                   // 16640, inside feat region

// Scratch (static device globals: no allocation allowed)
__device__ float g_agg[(size_t)MAXN * D_IN];
__device__ float g_den[MAXN];

// ---------------------------------------------------------------------------
// helpers
// ---------------------------------------------------------------------------
__device__ __forceinline__ unsigned f2tf(float f) {
    unsigned u;
    asm("cvt.rna.tf32.f32 %0, %1;" : "=r"(u) : "f"(f));
    return u;
}

__device__ __forceinline__ void mma_tf32(float* c, const unsigned* a,
                                         unsigned b0, unsigned b1) {
    asm volatile(
        "mma.sync.aligned.m16n8k8.row.col.f32.tf32.tf32.f32 "
        "{%0,%1,%2,%3},{%4,%5,%6,%7},{%8,%9},{%0,%1,%2,%3};\n"
        : "+f"(c[0]), "+f"(c[1]), "+f"(c[2]), "+f"(c[3])
        : "r"(a[0]), "r"(a[1]), "r"(a[2]), "r"(a[3]), "r"(b0), "r"(b1));
}

__device__ __forceinline__ void cp16(float* dst_smem, const float* src, bool pred) {
    unsigned d = (unsigned)__cvta_generic_to_shared(dst_smem);
    int sz = pred ? 16 : 0;
    asm volatile("cp.async.cg.shared.global [%0], [%1], 16, %2;\n"
                 :: "r"(d), "l"(src), "r"(sz));
}
__device__ __forceinline__ void cp_commit() {
    asm volatile("cp.async.commit_group;\n");
}
template <int N>
__device__ __forceinline__ void cp_wait() {
    asm volatile("cp.async.wait_group %0;\n" :: "n"(N));
}

// ---------------------------------------------------------------------------
// Kernel 1: zero the scratch
// ---------------------------------------------------------------------------
__global__ void zero_kernel(int N) {
    int idx = blockIdx.x * blockDim.x + threadIdx.x;
    int total = N * D_IN;
    if (idx < total) g_agg[idx] = 0.f;
    if (idx < N) g_den[idx] = 0.f;
}

// ---------------------------------------------------------------------------
// Kernel 2: masked scatter-add aggregation (warp per edge, float4 atomics)
// ---------------------------------------------------------------------------
__global__ void agg_kernel(const float* __restrict__ edge_attr,
                           const float* __restrict__ mask,
                           const int* __restrict__ edge_index, int E) {
    int w = (blockIdx.x * blockDim.x + threadIdx.x) >> 5;
    int lane = threadIdx.x & 31;
    if (w >= E) return;
    float m = mask[w];
    if (m == 0.f) return;
    int col = edge_index[E + w];
    const float4* a = (const float4*)(edge_attr + (size_t)w * D_IN);
    float4* dst = (float4*)(g_agg + (size_t)col * D_IN);
    float4 v = a[lane];
    v.x *= m; v.y *= m; v.z *= m; v.w *= m;
    atomicAdd(dst + lane, v);
    if (lane == 0) atomicAdd(g_den + col, m);
}

// ---------------------------------------------------------------------------
// Kernel 3: node_rep = concat(agg/den, x)  -> written straight into d_out
// ---------------------------------------------------------------------------
__global__ void noderep_kernel(const float* __restrict__ x,
                               float* __restrict__ out_node, int N) {
    int idx = blockIdx.x * blockDim.x + threadIdx.x;
    int total = N * D_NODEREP;
    if (idx >= total) return;
    int n = idx / D_NODEREP;
    int c = idx - n * D_NODEREP;
    float v;
    if (c < D_IN)
        v = g_agg[(size_t)n * D_IN + c] / (g_den[n] + 1.0f);
    else
        v = x[n * 6 + (c - D_IN)];
    out_node[idx] = v;
}

// ---------------------------------------------------------------------------
// Kernel 4: fused per-edge MLP on tf32 tensor cores.
// 64 edges / block, 512 threads (16 warps: wm=wid>>2 -> m16 tile, wn=wid&3).
// cp.async 3-stage weight pipeline, 1 barrier per chunk.
// ---------------------------------------------------------------------------
__global__ void __launch_bounds__(THREADS, 1)
edge_kernel(const float* __restrict__ node_rep,
            const float* __restrict__ edge_attr,
            const int* __restrict__ edge_index,
            const float* __restrict__ We, const float* __restrict__ bE,
            const float* __restrict__ W1, const float* __restrict__ b1,
            const float* __restrict__ W2, const float* __restrict__ b2,
            const float* __restrict__ g1, const float* __restrict__ be1,
            const float* __restrict__ g2, const float* __restrict__ be2,
            float* __restrict__ out, int E) {
    extern __shared__ float sm[];
    float* feat = sm + FEAT_OFF;
    float* hbuf = sm + H_OFF;
    float* wb = sm + WB_OFF;
    float* tbuf = sm + T_OFF;
    float* zbuf = sm + Z_OFF;
    __shared__ int rows_s[TILE_E], cols_s[TILE_E];

    const int tid = threadIdx.x;
    const int lane = tid & 31;
    const int wid = tid >> 5;
    const int e0 = blockIdx.x * TILE_E;

    const int m0 = 16 * (wid >> 2);   // warp row base (0,16,32,48)
    const int wn = wid & 3;
    const int r0 = lane >> 2;
    const int qk = lane & 3;
    const int cb = 2 * qk;

    // ---- weight chunk issue helpers (512 threads, 1024 x 16B per 16KB chunk)
    auto issue_we = [&](int ch, int stage) {  // We: 32 rows x 128 cols
        float* dst = wb + stage * WB_BUF;
        int kb = ch * 32;
#pragma unroll
        for (int j = 0; j < 2; j++) {
            int i = tid + j * THREADS;
            int r = i >> 5, c4 = (i & 31) * 4;
            cp16(dst + r * S_WA + c4, We + (size_t)(kb + r) * D_OUT + c4, (kb + r) < DCAT);
        }
        cp_commit();
    };
    auto issue_w1 = [&](int ch, int stage) {  // W1: 16 rows x 256 cols
        float* dst = wb + stage * WB_BUF;
        int kb = ch * 16;
#pragma unroll
        for (int j = 0; j < 2; j++) {
            int i = tid + j * THREADS;
            int r = i >> 6, c4 = (i & 63) * 4;
            cp16(dst + r * S_WB + c4, W1 + (size_t)(kb + r) * DH + c4, true);
        }
        cp_commit();
    };
    auto issue_w2 = [&](int ch, int stage) {  // W2: 32 rows x 128 cols
        float* dst = wb + stage * WB_BUF;
        int kb = ch * 32;
#pragma unroll
        for (int j = 0; j < 2; j++) {
            int i = tid + j * THREADS;
            int r = i >> 5, c4 = (i & 31) * 4;
            cp16(dst + r * S_WA + c4, W2 + (size_t)(kb + r) * D_OUT + c4, true);
        }
        cp_commit();
    };

    if (tid < TILE_E) {
        int eg = e0 + tid;
        rows_s[tid] = (eg < E) ? edge_index[eg] : 0;
        cols_s[tid] = (eg < E) ? edge_index[E + eg] : 0;
    }

    // prologue: start weight pipeline before the gather so cp.async overlaps it
    issue_we(0, 0);
    issue_we(1, 1);

    __syncthreads();

    // Gather edge_rep = [node_rep[row] | node_rep[col] | edge_attr] (+zero pad)
    for (int idx = tid; idx < TILE_E * KPAD; idx += THREADS) {
        int e = idx / KPAD;
        int k = idx - e * KPAD;
        int eg = e0 + e;
        float v = 0.f;
        if (eg < E && k < DCAT) {
            if (k < D_NODEREP)
                v = node_rep[(size_t)rows_s[e] * D_NODEREP + k];
            else if (k < 2 * D_NODEREP)
                v = node_rep[(size_t)cols_s[e] * D_NODEREP + (k - D_NODEREP)];
            else
                v = edge_attr[(size_t)eg * D_IN + (k - 2 * D_NODEREP)];
        }
        feat[e * S_FEAT + k] = v;
    }

    // ================= GEMM1: feat[64,416] @ We[416,128] =================
    {
        const int n0 = 32 * wn;
        float acc[4][4];
#pragma unroll
        for (int nt = 0; nt < 4; nt++)
#pragma unroll
            for (int q = 0; q < 4; q++) acc[nt][q] = 0.f;

        const int NCH = KPAD / 32;  // 13
        for (int ch = 0; ch < NCH; ch++) {
            if (ch < NCH - 2) cp_wait<1>(); else cp_wait<0>();
            __syncthreads();
            const float* cur = wb + (ch % NSTAGE) * WB_BUF;
#pragma unroll
            for (int ks = 0; ks < 4; ks++) {
                int k0 = ch * 32 + ks * 8;
                const float* ap = feat + (m0 + r0) * S_FEAT + k0 + qk;
                unsigned a[4];
                a[0] = f2tf(ap[0]);
                a[1] = f2tf(ap[8 * S_FEAT]);
                a[2] = f2tf(ap[4]);
                a[3] = f2tf(ap[8 * S_FEAT + 4]);
#pragma unroll
                for (int nt = 0; nt < 4; nt++) {
                    const float* bp = cur + (ks * 8 + qk) * S_WA + n0 + 8 * nt + r0;
                    mma_tf32(acc[nt], a, __float_as_uint(bp[0]),
                             __float_as_uint(bp[4 * S_WA]));
                }
            }
            if (ch + 2 < NCH) issue_we(ch + 2, (ch + 2) % NSTAGE);
        }

        // h = acc + bE + edge_attr residual (feat cols 268..395)
#pragma unroll
        for (int nt = 0; nt < 4; nt++) {
            int row = m0 + r0;
            int col = n0 + 8 * nt + cb;
#pragma unroll
            for (int q = 0; q < 4; q++) {
                int rr = row + (q >> 1) * 8;
                int cc = col + (q & 1);
                hbuf[rr * S_H + cc] =
                    acc[nt][q] + __ldg(&bE[cc]) + feat[rr * S_FEAT + 2 * D_NODEREP + cc];
            }
        }
    }
    __syncthreads();

    // start GEMM2 weight pipeline; overlaps LN1
    issue_w1(0, 0);
    issue_w1(1, 1);

    // ---------------- LayerNorm1 (in place on hbuf) ----------------
    for (int r = wid; r < TILE_E; r += 16) {
        float v[4], s = 0.f, s2 = 0.f;
#pragma unroll
        for (int q = 0; q < 4; q++) {
            v[q] = hbuf[r * S_H + lane + 32 * q];
            s += v[q];
            s2 += v[q] * v[q];
        }
#pragma unroll
        for (int off = 16; off > 0; off >>= 1) {
            s += __shfl_xor_sync(0xFFFFFFFF, s, off);
            s2 += __shfl_xor_sync(0xFFFFFFFF, s2, off);
        }
        float mu = s * (1.f / 128.f);
        float var = s2 * (1.f / 128.f) - mu * mu;
        float rinv = rsqrtf(var + EPS);
#pragma unroll
        for (int q = 0; q < 4; q++) {
            int c = lane + 32 * q;
            hbuf[r * S_H + c] = (v[q] - mu) * rinv * __ldg(&g1[c]) + __ldg(&be1[c]);
        }
    }

    // ================= GEMM2: h[64,128] @ W1[128,256], relu -> t ==========
    {
        const int n0 = 64 * wn;
        float acc[8][4];
#pragma unroll
        for (int nt = 0; nt < 8; nt++)
#pragma unroll
            for (int q = 0; q < 4; q++) acc[nt][q] = 0.f;

        const int NCH = D_OUT / 16;  // 8
        for (int ch = 0; ch < NCH; ch++) {
            if (ch < NCH - 2) cp_wait<1>(); else cp_wait<0>();
            __syncthreads();
            const float* cur = wb + (ch % NSTAGE) * WB_BUF;
#pragma unroll
            for (int ks = 0; ks < 2; ks++) {
                int k0 = ch * 16 + ks * 8;
                const float* ap = hbuf + (m0 + r0) * S_H + k0 + qk;
                unsigned a[4];
                a[0] = f2tf(ap[0]);
                a[1] = f2tf(ap[8 * S_H]);
                a[2] = f2tf(ap[4]);
                a[3] = f2tf(ap[8 * S_H + 4]);
#pragma unroll
                for (int nt = 0; nt < 8; nt++) {
                    const float* bp = cur + (ks * 8 + qk) * S_WB + n0 + 8 * nt + r0;
                    mma_tf32(acc[nt], a, __float_as_uint(bp[0]),
                             __float_as_uint(bp[4 * S_WB]));
                }
            }
            if (ch + 2 < NCH) issue_w1(ch + 2, (ch + 2) % NSTAGE);
        }

        // t = relu(acc + b1), stored tf32-rounded (GEMM3 A operand only)
#pragma unroll
        for (int nt = 0; nt < 8; nt++) {
            int row = m0 + r0;
            int col = n0 + 8 * nt + cb;
#pragma unroll
            for (int q = 0; q < 4; q++) {
                int rr = row + (q >> 1) * 8;
                int cc = col + (q & 1);
                float t = fmaxf(acc[nt][q] + __ldg(&b1[cc]), 0.f);
                tbuf[rr * S_T + cc] = __uint_as_float(f2tf(t));
            }
        }
    }
    __syncthreads();

    // start GEMM3 weight pipeline
    issue_w2(0, 0);
    issue_w2(1, 1);

    // ================= GEMM3: t[64,256] @ W2[256,128] ====================
    {
        const int n0 = 32 * wn;
        float acc[4][4];
#pragma unroll
        for (int nt = 0; nt < 4; nt++)
#pragma unroll
            for (int q = 0; q < 4; q++) acc[nt][q] = 0.f;

        const int NCH = DH / 32;  // 8
        for (int ch = 0; ch < NCH; ch++) {
            if (ch < NCH - 2) cp_wait<1>(); else cp_wait<0>();
            __syncthreads();
            const float* cur = wb + (ch % NSTAGE) * WB_BUF;
#pragma unroll
            for (int ks = 0; ks < 4; ks++) {
                int k0 = ch * 32 + ks * 8;
                const float* ap = tbuf + (m0 + r0) * S_T + k0 + qk;
                unsigned a[4];
                a[0] = __float_as_uint(ap[0]);
                a[1] = __float_as_uint(ap[8 * S_T]);
                a[2] = __float_as_uint(ap[4]);
                a[3] = __float_as_uint(ap[8 * S_T + 4]);
#pragma unroll
                for (int nt = 0; nt < 4; nt++) {
                    const float* bp = cur + (ks * 8 + qk) * S_WA + n0 + 8 * nt + r0;
                    mma_tf32(acc[nt], a, __float_as_uint(bp[0]),
                             __float_as_uint(bp[4 * S_WA]));
                }
            }
            if (ch + 2 < NCH) issue_w2(ch + 2, (ch + 2) % NSTAGE);
        }

        // z = acc + b2 + h (residual), to zbuf
#pragma unroll
        for (int nt = 0; nt < 4; nt++) {
            int row = m0 + r0;
            int col = n0 + 8 * nt + cb;
#pragma unroll
            for (int q = 0; q < 4; q++) {
                int rr = row + (q >> 1) * 8;
                int cc = col + (q & 1);
                zbuf[rr * S_H + cc] =
                    acc[nt][q] + __ldg(&b2[cc]) + hbuf[rr * S_H + cc];
            }
        }
    }
    __syncthreads();

    // ---------------- LayerNorm2 -> global out ----------------
    for (int r = wid; r < TILE_E; r += 16) {
        int eg = e0 + r;
        float v[4], s = 0.f, s2 = 0.f;
#pragma unroll
        for (int q = 0; q < 4; q++) {
            v[q] = zbuf[r * S_H + lane + 32 * q];
            s += v[q];
            s2 += v[q] * v[q];
        }
#pragma unroll
        for (int off = 16; off > 0; off >>= 1) {
            s += __shfl_xor_sync(0xFFFFFFFF, s, off);
            s2 += __shfl_xor_sync(0xFFFFFFFF, s2, off);
        }
        float mu = s * (1.f / 128.f);
        float var = s2 * (1.f / 128.f) - mu * mu;
        float rinv = rsqrtf(var + EPS);
        if (eg < E) {
#pragma unroll
            for (int q = 0; q < 4; q++) {
                int c = lane + 32 * q;
                out[(size_t)eg * D_OUT + c] = (v[q] - mu) * rinv * __ldg(&g2[c]) + __ldg(&be2[c]);
            }
        }
    }
}

// ---------------------------------------------------------------------------
// launch
// ---------------------------------------------------------------------------
extern "C" void kernel_launch(void* const* d_in, const int* in_sizes, int n_in,
                              void* d_out, int out_size) {
    const void* p[16];
    int sz[16];
    int m = 0;
    for (int i = 0; i < n_in && m < 16; i++) {
        if (in_sizes[i] == 1) continue;
        p[m] = d_in[i];
        sz[m] = in_sizes[i];
        m++;
    }
    const float* x          = (const float*)p[0];
    const int*   edge_index = (const int*)p[1];
    const float* edge_attr  = (const float*)p[2];
    const float* mask       = (const float*)p[3];
    const float* We         = (const float*)p[4];
    const float* bE         = (const float*)p[5];
    const float* W1         = (const float*)p[6];
    const float* b1         = (const float*)p[7];
    const float* W2         = (const float*)p[8];
    const float* b2         = (const float*)p[9];
    const float* g1         = (const float*)p[10];
    const float* be1        = (const float*)p[11];
    const float* g2         = (const float*)p[12];
    const float* be2        = (const float*)p[13];

    const int N = sz[0] / 6;
    const int E = sz[3];

    float* out_node = (float*)d_out;                     // [N,134]
    float* out_edge = out_node + (size_t)N * D_NODEREP;  // [E,128]

    {
        int total = N * D_IN;
        zero_kernel<<<(total + 255) / 256, 256>>>(N);
    }
    {
        agg_kernel<<<(E + 7) / 8, 256>>>(edge_attr, mask, edge_index, E);
    }
    {
        int total = N * D_NODEREP;
        noderep_kernel<<<(total + 255) / 256, 256>>>(x, out_node, N);
    }
    {
        const int smem = SMEM_FLOATS * (int)sizeof(float);
        cudaFuncSetAttribute(edge_kernel, cudaFuncAttributeMaxDynamicSharedMemorySize, smem);
        int blocks = (E + TILE_E - 1) / TILE_E;
        edge_kernel<<<blocks, THREADS, smem>>>(out_node, edge_attr, edge_index,
                                               We, bE, W1, b1, W2, b2,
                                               g1, be1, g2, be2, out_edge, E);
    }
}

// round 4
// speedup vs baseline: 6.3471x; 1.7267x over previous
#include <cuda_runtime.h>
#include <cuda_bf16.h>
#include <cstdint>

// ---------------------------------------------------------------------------
// Problem constants
// ---------------------------------------------------------------------------
#define MAXN 50000
#define D_IN 128
#define D_OUT 128
#define DCAT 396       // 3*128 + 2*6
#define D_NODEREP 134  // 128 + 6
#define DH 256
#define EPS 1e-5f

#define TILE_E 64
#define THREADS 512

// smem strides (floats) — conflict-free mma fragment LDS (stride mod 32 == 4)
#define S_H 132
#define S_T 260
#define S_WA 136       // 128-col weight chunks (mod 32 = 8)
#define S_WB 264       // 256-col weight chunks (mod 32 = 8)

// ---- edge kernel smem layout (floats) ----
#define FEATZ_OFF 0
#define FEATZ_FLOATS (TILE_E * S_H)            // 8448 (edge_attr tile, later z)
#define H_OFF FEATZ_FLOATS                     // 8448
#define H_FLOATS (TILE_E * S_H)                // 8448
#define T_OFF (H_OFF + H_FLOATS)               // 16896
#define T_FLOATS (TILE_E * S_T)                // 16640
#define WB_OFF (T_OFF + T_FLOATS)              // 33536
#define WB_BUF 4352                            // max(32*136, 16*264)
#define NSTAGE 3
#define SMEM_FLOATS (WB_OFF + NSTAGE * WB_BUF) // 46592 floats = 186.4 KB

// ---- node projection kernel ----
#define TILE_N 64
#define KPAD_P 144     // 134 padded to 16*9
#define NCH_P 9
#define S_P 164        // mod 32 = 4
#define NP_A_FLOATS (TILE_N * S_P)             // 10496
#define NP_WBUF 4224                           // 16*264
#define NP_SMEM (NP_A_FLOATS + NSTAGE * NP_WBUF) // 23168 floats = 92.7 KB

// Scratch (static device globals: no allocation allowed)
__device__ float g_agg[(size_t)MAXN * D_IN];
__device__ float g_den[MAXN];
__device__ float g_P[(size_t)MAXN * 256];      // [N][Pa(128) | Pb(128)]

// ---------------------------------------------------------------------------
// helpers
// ---------------------------------------------------------------------------
__device__ __forceinline__ unsigned f2tf(float f) {
    unsigned u;
    asm("cvt.rna.tf32.f32 %0, %1;" : "=r"(u) : "f"(f));
    return u;
}

__device__ __forceinline__ void mma_tf32(float* c, const unsigned* a,
                                         unsigned b0, unsigned b1) {
    asm volatile(
        "mma.sync.aligned.m16n8k8.row.col.f32.tf32.tf32.f32 "
        "{%0,%1,%2,%3},{%4,%5,%6,%7},{%8,%9},{%0,%1,%2,%3};\n"
        : "+f"(c[0]), "+f"(c[1]), "+f"(c[2]), "+f"(c[3])
        : "r"(a[0]), "r"(a[1]), "r"(a[2]), "r"(a[3]), "r"(b0), "r"(b1));
}

__device__ __forceinline__ void cp16(float* dst_smem, const float* src, bool pred) {
    unsigned d = (unsigned)__cvta_generic_to_shared(dst_smem);
    int sz = pred ? 16 : 0;
    asm volatile("cp.async.cg.shared.global [%0], [%1], 16, %2;\n"
                 :: "r"(d), "l"(src), "r"(sz));
}
__device__ __forceinline__ void cp_commit() {
    asm volatile("cp.async.commit_group;\n");
}
template <int N>
__device__ __forceinline__ void cp_wait() {
    asm volatile("cp.async.wait_group %0;\n" :: "n"(N));
}

// ---------------------------------------------------------------------------
// Kernel 1: zero the scratch
// ---------------------------------------------------------------------------
__global__ void zero_kernel(int N) {
    int idx = blockIdx.x * blockDim.x + threadIdx.x;
    int total = N * D_IN;
    if (idx < total) g_agg[idx] = 0.f;
    if (idx < N) g_den[idx] = 0.f;
}

// ---------------------------------------------------------------------------
// Kernel 2: masked scatter-add aggregation (warp per edge, float4 atomics)
// ---------------------------------------------------------------------------
__global__ void agg_kernel(const float* __restrict__ edge_attr,
                           const float* __restrict__ mask,
                           const int* __restrict__ edge_index, int E) {
    int w = (blockIdx.x * blockDim.x + threadIdx.x) >> 5;
    int lane = threadIdx.x & 31;
    if (w >= E) return;
    float m = mask[w];
    if (m == 0.f) return;
    int col = edge_index[E + w];
    const float4* a = (const float4*)(edge_attr + (size_t)w * D_IN);
    float4* dst = (float4*)(g_agg + (size_t)col * D_IN);
    float4 v = a[lane];
    v.x *= m; v.y *= m; v.z *= m; v.w *= m;
    atomicAdd(dst + lane, v);
    if (lane == 0) atomicAdd(g_den + col, m);
}

// ---------------------------------------------------------------------------
// Kernel 3: node_rep = concat(agg/den, x) -> straight into d_out
// ---------------------------------------------------------------------------
__global__ void noderep_kernel(const float* __restrict__ x,
                               float* __restrict__ out_node, int N) {
    int idx = blockIdx.x * blockDim.x + threadIdx.x;
    int total = N * D_NODEREP;
    if (idx >= total) return;
    int n = idx / D_NODEREP;
    int c = idx - n * D_NODEREP;
    float v;
    if (c < D_IN)
        v = g_agg[(size_t)n * D_IN + c] / (g_den[n] + 1.0f);
    else
        v = x[n * 6 + (c - D_IN)];
    out_node[idx] = v;
}

// ---------------------------------------------------------------------------
// Kernel 4: node projection  P = node_rep @ [We_a | We_b]   (N x 256)
// 64 nodes/block, 512 threads, tf32 mma, cp.async weight ring.
// ---------------------------------------------------------------------------
__global__ void __launch_bounds__(THREADS, 1)
nodeproj_kernel(const float* __restrict__ node_rep,
                const float* __restrict__ We, int N) {
    extern __shared__ float sm[];
    float* A = sm;
    float* wb = sm + NP_A_FLOATS;

    const int tid = threadIdx.x;
    const int lane = tid & 31;
    const int wid = tid >> 5;
    const int n0blk = blockIdx.x * TILE_N;

    const int m0 = 16 * (wid >> 2);
    const int n0 = 64 * (wid & 3);
    const int r0 = lane >> 2;
    const int qk = lane & 3;
    const int cb = 2 * qk;

    auto issue_w = [&](int ch, int stage) {  // 16 rows x 256 cols (Wea|Web)
        float* dst = wb + stage * NP_WBUF;
        int kb = ch * 16;
#pragma unroll
        for (int j = 0; j < 2; j++) {
            int i = tid + j * THREADS;
            int r = i >> 6;
            int c4 = (i & 63) * 4;
            int k = kb + r;
            const float* src = (c4 < 128)
                ? We + (size_t)k * D_OUT + c4
                : We + (size_t)(D_NODEREP + k) * D_OUT + (c4 - 128);
            cp16(dst + r * S_WB + c4, src, k < D_NODEREP);
        }
        cp_commit();
    };

    issue_w(0, 0);
    issue_w(1, 1);

    // stage A = node_rep rows [n0blk, n0blk+64), K padded to 144
    for (int idx = tid; idx < TILE_N * KPAD_P; idx += THREADS) {
        int e = idx / KPAD_P;
        int k = idx - e * KPAD_P;
        int n = n0blk + e;
        float v = (n < N && k < D_NODEREP) ? node_rep[(size_t)n * D_NODEREP + k] : 0.f;
        A[e * S_P + k] = v;
    }

    float acc[8][4];
#pragma unroll
    for (int nt = 0; nt < 8; nt++)
#pragma unroll
        for (int q = 0; q < 4; q++) acc[nt][q] = 0.f;

    for (int ch = 0; ch < NCH_P; ch++) {
        if (ch < NCH_P - 2) cp_wait<1>(); else cp_wait<0>();
        __syncthreads();
        const float* cur = wb + (ch % NSTAGE) * NP_WBUF;
#pragma unroll
        for (int ks = 0; ks < 2; ks++) {
            int k0 = ch * 16 + ks * 8;
            const float* ap = A + (m0 + r0) * S_P + k0 + qk;
            unsigned a[4];
            a[0] = f2tf(ap[0]);
            a[1] = f2tf(ap[8 * S_P]);
            a[2] = f2tf(ap[4]);
            a[3] = f2tf(ap[8 * S_P + 4]);
#pragma unroll
            for (int nt = 0; nt < 8; nt++) {
                const float* bp = cur + (ks * 8 + qk) * S_WB + n0 + 8 * nt + r0;
                mma_tf32(acc[nt], a, __float_as_uint(bp[0]),
                         __float_as_uint(bp[4 * S_WB]));
            }
        }
        if (ch + 2 < NCH_P) issue_w(ch + 2, (ch + 2) % NSTAGE);
    }

    // write P
#pragma unroll
    for (int nt = 0; nt < 8; nt++) {
        int col = n0 + 8 * nt + cb;
#pragma unroll
        for (int q = 0; q < 4; q++) {
            int rr = m0 + r0 + (q >> 1) * 8;
            int cc = col + (q & 1);
            int n = n0blk + rr;
            if (n < N) g_P[(size_t)n * 256 + cc] = acc[nt][q];
        }
    }
}

// ---------------------------------------------------------------------------
// Kernel 5: fused edge MLP.
//   h = LN1(edge_attr@We_c + Pa[row] + Pb[col] + bE + edge_attr)
//   out = LN2(h + relu(h@W1+b1)@W2 + b2)
// 64 edges/block, 512 threads (16 warps), tf32 mma, cp.async weight ring.
// ---------------------------------------------------------------------------
__global__ void __launch_bounds__(THREADS, 1)
edge_kernel(const float* __restrict__ edge_attr,
            const int* __restrict__ edge_index,
            const float* __restrict__ We, const float* __restrict__ bE,
            const float* __restrict__ W1, const float* __restrict__ b1,
            const float* __restrict__ W2, const float* __restrict__ b2,
            const float* __restrict__ g1, const float* __restrict__ be1,
            const float* __restrict__ g2, const float* __restrict__ be2,
            float* __restrict__ out, int E) {
    extern __shared__ float sm[];
    float* featz = sm + FEATZ_OFF;  // edge_attr tile; reused as z after GEMM1
    float* hbuf = sm + H_OFF;
    float* tbuf = sm + T_OFF;
    float* wb = sm + WB_OFF;
    __shared__ int rows_s[TILE_E], cols_s[TILE_E];

    const int tid = threadIdx.x;
    const int lane = tid & 31;
    const int wid = tid >> 5;
    const int e0 = blockIdx.x * TILE_E;

    const int m0 = 16 * (wid >> 2);
    const int wn = wid & 3;
    const int r0 = lane >> 2;
    const int qk = lane & 3;
    const int cb = 2 * qk;

    auto issue_wec = [&](int ch, int stage) {  // We_c: rows 268+.. , 32x128
        float* dst = wb + stage * WB_BUF;
        int kb = ch * 32;
#pragma unroll
        for (int j = 0; j < 2; j++) {
            int i = tid + j * THREADS;
            int r = i >> 5, c4 = (i & 31) * 4;
            cp16(dst + r * S_WA + c4,
                 We + (size_t)(2 * D_NODEREP + kb + r) * D_OUT + c4, true);
        }
        cp_commit();
    };
    auto issue_w1 = [&](int ch, int stage) {  // W1: 16 x 256
        float* dst = wb + stage * WB_BUF;
        int kb = ch * 16;
#pragma unroll
        for (int j = 0; j < 2; j++) {
            int i = tid + j * THREADS;
            int r = i >> 6, c4 = (i & 63) * 4;
            cp16(dst + r * S_WB + c4, W1 + (size_t)(kb + r) * DH + c4, true);
        }
        cp_commit();
    };
    auto issue_w2 = [&](int ch, int stage) {  // W2: 32 x 128
        float* dst = wb + stage * WB_BUF;
        int kb = ch * 32;
#pragma unroll
        for (int j = 0; j < 2; j++) {
            int i = tid + j * THREADS;
            int r = i >> 5, c4 = (i & 31) * 4;
            cp16(dst + r * S_WA + c4, W2 + (size_t)(kb + r) * D_OUT + c4, true);
        }
        cp_commit();
    };

    if (tid < TILE_E) {
        int eg = e0 + tid;
        rows_s[tid] = (eg < E) ? edge_index[eg] : 0;
        cols_s[tid] = (eg < E) ? edge_index[E + eg] : 0;
    }

    issue_wec(0, 0);
    issue_wec(1, 1);

    // edge_attr tile -> featz (float4 coalesced)
    for (int idx = tid; idx < TILE_E * 32; idx += THREADS) {
        int e = idx >> 5;
        int c4 = (idx & 31) * 4;
        int eg = e0 + e;
        float4 v = make_float4(0.f, 0.f, 0.f, 0.f);
        if (eg < E) v = *(const float4*)(edge_attr + (size_t)eg * D_IN + c4);
        *(float4*)(featz + e * S_H + c4) = v;
    }
    __syncthreads();  // rows_s/cols_s ready

    // hbuf = Pa[row] + Pb[col]  (float4 coalesced gather from L2-resident P)
    for (int idx = tid; idx < TILE_E * 32; idx += THREADS) {
        int e = idx >> 5;
        int c4 = (idx & 31) * 4;
        float4 pa = *(const float4*)(g_P + (size_t)rows_s[e] * 256 + c4);
        float4 pb = *(const float4*)(g_P + (size_t)cols_s[e] * 256 + 128 + c4);
        pa.x += pb.x; pa.y += pb.y; pa.z += pb.z; pa.w += pb.w;
        *(float4*)(hbuf + e * S_H + c4) = pa;
    }

    // ================= GEMM1': featz[64,128] @ We_c[128,128] ==============
    {
        const int n0 = 32 * wn;
        float acc[4][4];
#pragma unroll
        for (int nt = 0; nt < 4; nt++)
#pragma unroll
            for (int q = 0; q < 4; q++) acc[nt][q] = 0.f;

        const int NCH = 4;
        for (int ch = 0; ch < NCH; ch++) {
            if (ch < NCH - 2) cp_wait<1>(); else cp_wait<0>();
            __syncthreads();
            const float* cur = wb + (ch % NSTAGE) * WB_BUF;
#pragma unroll
            for (int ks = 0; ks < 4; ks++) {
                int k0 = ch * 32 + ks * 8;
                const float* ap = featz + (m0 + r0) * S_H + k0 + qk;
                unsigned a[4];
                a[0] = f2tf(ap[0]);
                a[1] = f2tf(ap[8 * S_H]);
                a[2] = f2tf(ap[4]);
                a[3] = f2tf(ap[8 * S_H + 4]);
#pragma unroll
                for (int nt = 0; nt < 4; nt++) {
                    const float* bp = cur + (ks * 8 + qk) * S_WA + n0 + 8 * nt + r0;
                    mma_tf32(acc[nt], a, __float_as_uint(bp[0]),
                             __float_as_uint(bp[4 * S_WA]));
                }
            }
            if (ch + 2 < NCH) issue_wec(ch + 2, (ch + 2) % NSTAGE);
        }

        // h += acc + bE + edge_attr residual
#pragma unroll
        for (int nt = 0; nt < 4; nt++) {
            int col = 32 * wn + 8 * nt + cb;
#pragma unroll
            for (int q = 0; q < 4; q++) {
                int rr = m0 + r0 + (q >> 1) * 8;
                int cc = col + (q & 1);
                hbuf[rr * S_H + cc] +=
                    acc[nt][q] + __ldg(&bE[cc]) + featz[rr * S_H + cc];
            }
        }
    }
    __syncthreads();

    issue_w1(0, 0);
    issue_w1(1, 1);

    // ---------------- LayerNorm1 (in place on hbuf) ----------------
    for (int r = wid; r < TILE_E; r += 16) {
        float v[4], s = 0.f, s2 = 0.f;
#pragma unroll
        for (int q = 0; q < 4; q++) {
            v[q] = hbuf[r * S_H + lane + 32 * q];
            s += v[q];
            s2 += v[q] * v[q];
        }
#pragma unroll
        for (int off = 16; off > 0; off >>= 1) {
            s += __shfl_xor_sync(0xFFFFFFFF, s, off);
            s2 += __shfl_xor_sync(0xFFFFFFFF, s2, off);
        }
        float mu = s * (1.f / 128.f);
        float var = s2 * (1.f / 128.f) - mu * mu;
        float rinv = rsqrtf(var + EPS);
#pragma unroll
        for (int q = 0; q < 4; q++) {
            int c = lane + 32 * q;
            hbuf[r * S_H + c] = (v[q] - mu) * rinv * __ldg(&g1[c]) + __ldg(&be1[c]);
        }
    }

    // ================= GEMM2: h[64,128] @ W1[128,256], relu -> t ==========
    {
        const int n0 = 64 * wn;
        float acc[8][4];
#pragma unroll
        for (int nt = 0; nt < 8; nt++)
#pragma unroll
            for (int q = 0; q < 4; q++) acc[nt][q] = 0.f;

        const int NCH = 8;
        for (int ch = 0; ch < NCH; ch++) {
            if (ch < NCH - 2) cp_wait<1>(); else cp_wait<0>();
            __syncthreads();
            const float* cur = wb + (ch % NSTAGE) * WB_BUF;
#pragma unroll
            for (int ks = 0; ks < 2; ks++) {
                int k0 = ch * 16 + ks * 8;
                const float* ap = hbuf + (m0 + r0) * S_H + k0 + qk;
                unsigned a[4];
                a[0] = f2tf(ap[0]);
                a[1] = f2tf(ap[8 * S_H]);
                a[2] = f2tf(ap[4]);
                a[3] = f2tf(ap[8 * S_H + 4]);
#pragma unroll
                for (int nt = 0; nt < 8; nt++) {
                    const float* bp = cur + (ks * 8 + qk) * S_WB + n0 + 8 * nt + r0;
                    mma_tf32(acc[nt], a, __float_as_uint(bp[0]),
                             __float_as_uint(bp[4 * S_WB]));
                }
            }
            if (ch + 2 < NCH) issue_w1(ch + 2, (ch + 2) % NSTAGE);
        }

        // t = relu(acc + b1), tf32-rounded for GEMM3 A
#pragma unroll
        for (int nt = 0; nt < 8; nt++) {
            int col = 64 * wn + 8 * nt + cb;
#pragma unroll
            for (int q = 0; q < 4; q++) {
                int rr = m0 + r0 + (q >> 1) * 8;
                int cc = col + (q & 1);
                float t = fmaxf(acc[nt][q] + __ldg(&b1[cc]), 0.f);
                tbuf[rr * S_T + cc] = __uint_as_float(f2tf(t));
            }
        }
    }
    __syncthreads();

    issue_w2(0, 0);
    issue_w2(1, 1);

    // ================= GEMM3: t[64,256] @ W2[256,128] ====================
    {
        const int n0 = 32 * wn;
        float acc[4][4];
#pragma unroll
        for (int nt = 0; nt < 4; nt++)
#pragma unroll
            for (int q = 0; q < 4; q++) acc[nt][q] = 0.f;

        const int NCH = 8;
        for (int ch = 0; ch < NCH; ch++) {
            if (ch < NCH - 2) cp_wait<1>(); else cp_wait<0>();
            __syncthreads();
            const float* cur = wb + (ch % NSTAGE) * WB_BUF;
#pragma unroll
            for (int ks = 0; ks < 4; ks++) {
                int k0 = ch * 32 + ks * 8;
                const float* ap = tbuf + (m0 + r0) * S_T + k0 + qk;
                unsigned a[4];
                a[0] = __float_as_uint(ap[0]);
                a[1] = __float_as_uint(ap[8 * S_T]);
                a[2] = __float_as_uint(ap[4]);
                a[3] = __float_as_uint(ap[8 * S_T + 4]);
#pragma unroll
                for (int nt = 0; nt < 4; nt++) {
                    const float* bp = cur + (ks * 8 + qk) * S_WA + n0 + 8 * nt + r0;
                    mma_tf32(acc[nt], a, __float_as_uint(bp[0]),
                             __float_as_uint(bp[4 * S_WA]));
                }
            }
            if (ch + 2 < NCH) issue_w2(ch + 2, (ch + 2) % NSTAGE);
        }

        // z = acc + b2 + h  -> featz (edge_attr tile is dead now)
#pragma unroll
        for (int nt = 0; nt < 4; nt++) {
            int col = 32 * wn + 8 * nt + cb;
#pragma unroll
            for (int q = 0; q < 4; q++) {
                int rr = m0 + r0 + (q >> 1) * 8;
                int cc = col + (q & 1);
                featz[rr * S_H + cc] =
                    acc[nt][q] + __ldg(&b2[cc]) + hbuf[rr * S_H + cc];
            }
        }
    }
    __syncthreads();

    // ---------------- LayerNorm2 -> global out ----------------
    for (int r = wid; r < TILE_E; r += 16) {
        int eg = e0 + r;
        float v[4], s = 0.f, s2 = 0.f;
#pragma unroll
        for (int q = 0; q < 4; q++) {
            v[q] = featz[r * S_H + lane + 32 * q];
            s += v[q];
            s2 += v[q] * v[q];
        }
#pragma unroll
        for (int off = 16; off > 0; off >>= 1) {
            s += __shfl_xor_sync(0xFFFFFFFF, s, off);
            s2 += __shfl_xor_sync(0xFFFFFFFF, s2, off);
        }
        float mu = s * (1.f / 128.f);
        float var = s2 * (1.f / 128.f) - mu * mu;
        float rinv = rsqrtf(var + EPS);
        if (eg < E) {
#pragma unroll
            for (int q = 0; q < 4; q++) {
                int c = lane + 32 * q;
                out[(size_t)eg * D_OUT + c] = (v[q] - mu) * rinv * __ldg(&g2[c]) + __ldg(&be2[c]);
            }
        }
    }
}

// ---------------------------------------------------------------------------
// launch
// ---------------------------------------------------------------------------
extern "C" void kernel_launch(void* const* d_in, const int* in_sizes, int n_in,
                              void* d_out, int out_size) {
    const void* p[16];
    int sz[16];
    int m = 0;
    for (int i = 0; i < n_in && m < 16; i++) {
        if (in_sizes[i] == 1) continue;
        p[m] = d_in[i];
        sz[m] = in_sizes[i];
        m++;
    }
    const float* x          = (const float*)p[0];
    const int*   edge_index = (const int*)p[1];
    const float* edge_attr  = (const float*)p[2];
    const float* mask       = (const float*)p[3];
    const float* We         = (const float*)p[4];
    const float* bE         = (const float*)p[5];
    const float* W1         = (const float*)p[6];
    const float* b1         = (const float*)p[7];
    const float* W2         = (const float*)p[8];
    const float* b2         = (const float*)p[9];
    const float* g1         = (const float*)p[10];
    const float* be1        = (const float*)p[11];
    const float* g2         = (const float*)p[12];
    const float* be2        = (const float*)p[13];

    const int N = sz[0] / 6;
    const int E = sz[3];

    float* out_node = (float*)d_out;                     // [N,134]
    float* out_edge = out_node + (size_t)N * D_NODEREP;  // [E,128]

    {
        int total = N * D_IN;
        zero_kernel<<<(total + 255) / 256, 256>>>(N);
    }
    {
        agg_kernel<<<(E + 7) / 8, 256>>>(edge_attr, mask, edge_index, E);
    }
    {
        int total = N * D_NODEREP;
        noderep_kernel<<<(total + 255) / 256, 256>>>(x, out_node, N);
    }
    {
        const int smem = NP_SMEM * (int)sizeof(float);
        cudaFuncSetAttribute(nodeproj_kernel, cudaFuncAttributeMaxDynamicSharedMemorySize, smem);
        int blocks = (N + TILE_N - 1) / TILE_N;
        nodeproj_kernel<<<blocks, THREADS, smem>>>(out_node, We, N);
    }
    {
        const int smem = SMEM_FLOATS * (int)sizeof(float);
        cudaFuncSetAttribute(edge_kernel, cudaFuncAttributeMaxDynamicSharedMemorySize, smem);
        int blocks = (E + TILE_E - 1) / TILE_E;
        edge_kernel<<<blocks, THREADS, smem>>>(edge_attr, edge_index,
                                               We, bE, W1, b1, W2, b2,
                                               g1, be1, g2, be2, out_edge, E);
    }
}

// round 6
// speedup vs baseline: 7.9951x; 1.2596x over previous
#include <cuda_runtime.h>
#include <cuda_bf16.h>
#include <cstdint>

// ---------------------------------------------------------------------------
// Problem constants
// ---------------------------------------------------------------------------
#define MAXN 50000
#define D_IN 128
#define D_OUT 128
#define D_NODEREP 134  // 128 + 6
#define DH 256
#define EPS 1e-5f

#define TILE_E 64
#define ETHREADS 256

// smem strides (floats) — conflict-free mma fragment LDS
#define S_H 132        // mod 32 = 4
#define S_WA 136       // 128-col weight chunks (mod 32 = 8)
#define S_WB 264       // 256-col weight chunks (mod 32 = 8)

// ---- edge kernel smem layout (floats) ----
#define HBUF_OFF 0
#define HBUF_FLOATS (TILE_E * S_H)             // 8448
#define TZ_OFF HBUF_FLOATS                     // featz / t-half / z overlay
#define TZ_FLOATS (TILE_E * S_H)               // 8448
#define WB_OFF (TZ_OFF + TZ_FLOATS)            // 16896
#define WB_BUF 4352                            // 32 rows * 136
#define E_SMEM_FLOATS (WB_OFF + 2 * WB_BUF)    // 25600 floats = 102.4 KB

// ---- node projection kernel ----
#define TILE_N 64
#define NPTHREADS 256
#define KPAD_P 144     // 134 padded to 16*9
#define NCH_P 9
#define S_P 164        // mod 32 = 4
#define NP_A_FLOATS (TILE_N * S_P)             // 10496
#define NP_WBUF 4224                           // 16 * 264
#define NP_SMEM_FLOATS (NP_A_FLOATS + 2 * NP_WBUF)  // 18944 floats = 75.8 KB

// Scratch (static device globals: no allocation allowed)
__device__ float g_agg[(size_t)MAXN * D_IN];
__device__ float g_den[MAXN];
__device__ float g_P[(size_t)MAXN * 256];      // [N][Pa(128) | Pb(128)]

// ---------------------------------------------------------------------------
// helpers
// ---------------------------------------------------------------------------
__device__ __forceinline__ unsigned f2tf(float f) {
    unsigned u;
    asm("cvt.rna.tf32.f32 %0, %1;" : "=r"(u) : "f"(f));
    return u;
}

__device__ __forceinline__ void mma_tf32(float* c, const unsigned* a,
                                         unsigned b0, unsigned b1) {
    asm volatile(
        "mma.sync.aligned.m16n8k8.row.col.f32.tf32.tf32.f32 "
        "{%0,%1,%2,%3},{%4,%5,%6,%7},{%8,%9},{%0,%1,%2,%3};\n"
        : "+f"(c[0]), "+f"(c[1]), "+f"(c[2]), "+f"(c[3])
        : "r"(a[0]), "r"(a[1]), "r"(a[2]), "r"(a[3]), "r"(b0), "r"(b1));
}

__device__ __forceinline__ void cp16(float* dst_smem, const float* src, bool pred) {
    unsigned d = (unsigned)__cvta_generic_to_shared(dst_smem);
    int sz = pred ? 16 : 0;
    asm volatile("cp.async.cg.shared.global [%0], [%1], 16, %2;\n"
                 :: "r"(d), "l"(src), "r"(sz));
}
__device__ __forceinline__ void cp_commit() {
    asm volatile("cp.async.commit_group;\n");
}
template <int N>
__device__ __forceinline__ void cp_wait() {
    asm volatile("cp.async.wait_group %0;\n" :: "n"(N));
}

// ---------------------------------------------------------------------------
// Kernel 1: zero the scratch
// ---------------------------------------------------------------------------
__global__ void zero_kernel(int N) {
    int idx = blockIdx.x * blockDim.x + threadIdx.x;
    int total = N * D_IN;
    if (idx < total) g_agg[idx] = 0.f;
    if (idx < N) g_den[idx] = 0.f;
}

// ---------------------------------------------------------------------------
// Kernel 2: masked scatter-add aggregation (warp per edge, float4 atomics)
// ---------------------------------------------------------------------------
__global__ void agg_kernel(const float* __restrict__ edge_attr,
                           const float* __restrict__ mask,
                           const int* __restrict__ edge_index, int E) {
    int w = (blockIdx.x * blockDim.x + threadIdx.x) >> 5;
    int lane = threadIdx.x & 31;
    if (w >= E) return;
    float m = mask[w];
    if (m == 0.f) return;
    int col = edge_index[E + w];
    const float4* a = (const float4*)(edge_attr + (size_t)w * D_IN);
    float4* dst = (float4*)(g_agg + (size_t)col * D_IN);
    float4 v = a[lane];
    v.x *= m; v.y *= m; v.z *= m; v.w *= m;
    atomicAdd(dst + lane, v);
    if (lane == 0) atomicAdd(g_den + col, m);
}

// ---------------------------------------------------------------------------
// Kernel 3: node projection  P = node_rep @ [We_a | We_b]   (N x 256)
// Also materializes node_rep into out_node.
// 64 nodes/block, 256 threads (8 warps: m16 x n128 warp tile), 2-stage ring.
// Race-free pipeline order: wait -> barrier -> issue(ch+1) -> compute(ch).
// ---------------------------------------------------------------------------
__global__ void __launch_bounds__(NPTHREADS, 2)
nodeproj_kernel(const float* __restrict__ x,
                const float* __restrict__ We,
                float* __restrict__ out_node, int N) {
    extern __shared__ float sm[];
    float* A = sm;
    float* wb = sm + NP_A_FLOATS;
    __shared__ float rden_s[TILE_N];

    const int tid = threadIdx.x;
    const int lane = tid & 31;
    const int wid = tid >> 5;
    const int n0blk = blockIdx.x * TILE_N;

    const int m0 = 16 * (wid >> 1);
    const int n0 = 128 * (wid & 1);
    const int r0 = lane >> 2;
    const int qk = lane & 3;
    const int cb = 2 * qk;

    auto issue_w = [&](int ch, int stage) {  // 16 rows x 256 cols (Wea|Web)
        float* dst = wb + stage * NP_WBUF;
        int kb = ch * 16;
#pragma unroll
        for (int j = 0; j < 4; j++) {
            int i = tid + j * NPTHREADS;
            int r = i >> 6;
            int c4 = (i & 63) * 4;
            int k = kb + r;
            const float* src = (c4 < 128)
                ? We + (size_t)k * D_OUT + c4
                : We + (size_t)(D_NODEREP + k) * D_OUT + (c4 - 128);
            cp16(dst + r * S_WB + c4, src, k < D_NODEREP);
        }
        cp_commit();
    };

    issue_w(0, 0);

    // per-row 1/(den+1)
    if (tid < TILE_N) {
        int n = n0blk + tid;
        float d = (n < N) ? g_den[n] : 0.f;
        rden_s[tid] = 1.0f / (d + 1.0f);
    }
    __syncthreads();

    // stage A = node_rep rows (computed inline), write node_rep output too
    for (int idx = tid; idx < TILE_N * KPAD_P; idx += NPTHREADS) {
        int e = idx / KPAD_P;
        int k = idx - e * KPAD_P;
        int n = n0blk + e;
        float v = 0.f;
        if (n < N && k < D_NODEREP) {
            if (k < D_IN)
                v = g_agg[(size_t)n * D_IN + k] * rden_s[e];
            else
                v = x[n * 6 + (k - D_IN)];
            out_node[(size_t)n * D_NODEREP + k] = v;
        }
        A[e * S_P + k] = v;
    }

    float acc[16][4];
#pragma unroll
    for (int nt = 0; nt < 16; nt++)
#pragma unroll
        for (int q = 0; q < 4; q++) acc[nt][q] = 0.f;

    for (int ch = 0; ch < NCH_P; ch++) {
        cp_wait<0>();
        __syncthreads();
        if (ch + 1 < NCH_P) issue_w(ch + 1, (ch + 1) & 1);
        const float* cur = wb + (ch & 1) * NP_WBUF;
#pragma unroll
        for (int ks = 0; ks < 2; ks++) {
            int k0 = ch * 16 + ks * 8;
            const float* ap = A + (m0 + r0) * S_P + k0 + qk;
            unsigned a[4];
            a[0] = f2tf(ap[0]);
            a[1] = f2tf(ap[8 * S_P]);
            a[2] = f2tf(ap[4]);
            a[3] = f2tf(ap[8 * S_P + 4]);
#pragma unroll
            for (int nt = 0; nt < 16; nt++) {
                const float* bp = cur + (ks * 8 + qk) * S_WB + n0 + 8 * nt + r0;
                mma_tf32(acc[nt], a, __float_as_uint(bp[0]),
                         __float_as_uint(bp[4 * S_WB]));
            }
        }
    }

    // write P
#pragma unroll
    for (int nt = 0; nt < 16; nt++) {
        int col = n0 + 8 * nt + cb;
#pragma unroll
        for (int q = 0; q < 4; q++) {
            int rr = m0 + r0 + (q >> 1) * 8;
            int cc = col + (q & 1);
            int n = n0blk + rr;
            if (n < N) g_P[(size_t)n * 256 + cc] = acc[nt][q];
        }
    }
}

// ---------------------------------------------------------------------------
// Kernel 4: fused edge MLP.
//   h = LN1(edge_attr@We_c + Pa[row] + Pb[col] + bE + edge_attr)
//   out = LN2(h + relu(h@W1+b1)@W2 + b2)   (GEMM2/3 done in two 128-halves)
// 64 edges/block, 256 threads (8 warps, warp tile m16 x n64), 2 blocks/SM.
// Race-free pipeline order: wait -> barrier -> issue(ch+1) -> compute(ch).
// ---------------------------------------------------------------------------
__global__ void __launch_bounds__(ETHREADS, 2)
edge_kernel(const float* __restrict__ edge_attr,
            const int* __restrict__ edge_index,
            const float* __restrict__ We, const float* __restrict__ bE,
            const float* __restrict__ W1, const float* __restrict__ b1,
            const float* __restrict__ W2, const float* __restrict__ b2,
            const float* __restrict__ g1, const float* __restrict__ be1,
            const float* __restrict__ g2, const float* __restrict__ be2,
            float* __restrict__ out, int E) {
    extern __shared__ float sm[];
    float* hbuf = sm + HBUF_OFF;
    float* tz = sm + TZ_OFF;    // featz -> t-half -> z overlay
    float* wb = sm + WB_OFF;
    __shared__ int rows_s[TILE_E], cols_s[TILE_E];

    const int tid = threadIdx.x;
    const int lane = tid & 31;
    const int wid = tid >> 5;
    const int e0 = blockIdx.x * TILE_E;

    const int m0 = 16 * (wid >> 1);   // 0,16,32,48
    const int n064 = 64 * (wid & 1);  // 0 or 64
    const int r0 = lane >> 2;
    const int qk = lane & 3;
    const int cb = 2 * qk;

    auto issue_wec = [&](int ch, int stage) {  // We_c rows 268+ch*32.., 32x128
        float* dst = wb + stage * WB_BUF;
        int kb = ch * 32;
#pragma unroll
        for (int j = 0; j < 4; j++) {
            int i = tid + j * ETHREADS;
            int r = i >> 5, c4 = (i & 31) * 4;
            cp16(dst + r * S_WA + c4,
                 We + (size_t)(2 * D_NODEREP + kb + r) * D_OUT + c4, true);
        }
        cp_commit();
    };
    auto issue_w1h = [&](int hf, int ch, int stage) {  // W1 16 x 128 (half hf)
        float* dst = wb + stage * WB_BUF;
        int kb = ch * 16;
#pragma unroll
        for (int j = 0; j < 2; j++) {
            int i = tid + j * ETHREADS;
            int r = i >> 5, c4 = (i & 31) * 4;
            cp16(dst + r * S_WA + c4,
                 W1 + (size_t)(kb + r) * DH + hf * 128 + c4, true);
        }
        cp_commit();
    };
    auto issue_w2h = [&](int hf, int ch, int stage) {  // W2 32 x 128 (rows half)
        float* dst = wb + stage * WB_BUF;
        int kb = hf * 128 + ch * 32;
#pragma unroll
        for (int j = 0; j < 4; j++) {
            int i = tid + j * ETHREADS;
            int r = i >> 5, c4 = (i & 31) * 4;
            cp16(dst + r * S_WA + c4, W2 + (size_t)(kb + r) * D_OUT + c4, true);
        }
        cp_commit();
    };

    if (tid < TILE_E) {
        int eg = e0 + tid;
        rows_s[tid] = (eg < E) ? edge_index[eg] : 0;
        cols_s[tid] = (eg < E) ? edge_index[E + eg] : 0;
    }

    issue_wec(0, 0);

    // edge_attr tile -> tz (featz), float4 coalesced
    for (int idx = tid; idx < TILE_E * 32; idx += ETHREADS) {
        int e = idx >> 5;
        int c4 = (idx & 31) * 4;
        int eg = e0 + e;
        float4 v = make_float4(0.f, 0.f, 0.f, 0.f);
        if (eg < E) v = *(const float4*)(edge_attr + (size_t)eg * D_IN + c4);
        *(float4*)(tz + e * S_H + c4) = v;
    }
    __syncthreads();  // rows_s/cols_s ready

    // hbuf = Pa[row] + Pb[col]  (float4 gather from L2-resident P)
    for (int idx = tid; idx < TILE_E * 32; idx += ETHREADS) {
        int e = idx >> 5;
        int c4 = (idx & 31) * 4;
        float4 pa = *(const float4*)(g_P + (size_t)rows_s[e] * 256 + c4);
        float4 pb = *(const float4*)(g_P + (size_t)cols_s[e] * 256 + 128 + c4);
        pa.x += pb.x; pa.y += pb.y; pa.z += pb.z; pa.w += pb.w;
        *(float4*)(hbuf + e * S_H + c4) = pa;
    }

    // ================= GEMM1: featz[64,128] @ We_c[128,128] ==============
    {
        float acc[8][4];
#pragma unroll
        for (int nt = 0; nt < 8; nt++)
#pragma unroll
            for (int q = 0; q < 4; q++) acc[nt][q] = 0.f;

        const int NCH = 4;
        for (int ch = 0; ch < NCH; ch++) {
            cp_wait<0>();
            __syncthreads();
            if (ch + 1 < NCH) issue_wec(ch + 1, (ch + 1) & 1);
            const float* cur = wb + (ch & 1) * WB_BUF;
#pragma unroll
            for (int ks = 0; ks < 4; ks++) {
                int k0 = ch * 32 + ks * 8;
                const float* ap = tz + (m0 + r0) * S_H + k0 + qk;
                unsigned a[4];
                a[0] = f2tf(ap[0]);
                a[1] = f2tf(ap[8 * S_H]);
                a[2] = f2tf(ap[4]);
                a[3] = f2tf(ap[8 * S_H + 4]);
#pragma unroll
                for (int nt = 0; nt < 8; nt++) {
                    const float* bp = cur + (ks * 8 + qk) * S_WA + n064 + 8 * nt + r0;
                    mma_tf32(acc[nt], a, __float_as_uint(bp[0]),
                             __float_as_uint(bp[4 * S_WA]));
                }
            }
        }

        // h += acc + bE + edge_attr residual (featz)
#pragma unroll
        for (int nt = 0; nt < 8; nt++) {
            int col = n064 + 8 * nt + cb;
#pragma unroll
            for (int q = 0; q < 4; q++) {
                int rr = m0 + r0 + (q >> 1) * 8;
                int cc = col + (q & 1);
                hbuf[rr * S_H + cc] +=
                    acc[nt][q] + __ldg(&bE[cc]) + tz[rr * S_H + cc];
            }
        }
    }
    __syncthreads();

    // ---------------- LayerNorm1 (in place on hbuf) ----------------
    for (int r = wid; r < TILE_E; r += 8) {
        float v[4], s = 0.f, s2 = 0.f;
#pragma unroll
        for (int q = 0; q < 4; q++) {
            v[q] = hbuf[r * S_H + lane + 32 * q];
            s += v[q];
            s2 += v[q] * v[q];
        }
#pragma unroll
        for (int off = 16; off > 0; off >>= 1) {
            s += __shfl_xor_sync(0xFFFFFFFF, s, off);
            s2 += __shfl_xor_sync(0xFFFFFFFF, s2, off);
        }
        float mu = s * (1.f / 128.f);
        float var = s2 * (1.f / 128.f) - mu * mu;
        float rinv = rsqrtf(var + EPS);
#pragma unroll
        for (int q = 0; q < 4; q++) {
            int c = lane + 32 * q;
            hbuf[r * S_H + c] = (v[q] - mu) * rinv * __ldg(&g1[c]) + __ldg(&be1[c]);
        }
    }
    __syncthreads();

    // ============ GEMM2+GEMM3 in two 128-halves, acc3 persistent =========
    float acc3[8][4];
#pragma unroll
    for (int nt = 0; nt < 8; nt++)
#pragma unroll
        for (int q = 0; q < 4; q++) acc3[nt][q] = 0.f;

#pragma unroll 1
    for (int hf = 0; hf < 2; hf++) {
        // ---- GEMM2 half: t_half = relu(h @ W1[:, hf*128:+128] + b1h) ----
        {
            float acc2[8][4];
#pragma unroll
            for (int nt = 0; nt < 8; nt++)
#pragma unroll
                for (int q = 0; q < 4; q++) acc2[nt][q] = 0.f;

            issue_w1h(hf, 0, 0);
            const int NCH = 8;
            for (int ch = 0; ch < NCH; ch++) {
                cp_wait<0>();
                __syncthreads();
                if (ch + 1 < NCH) issue_w1h(hf, ch + 1, (ch + 1) & 1);
                const float* cur = wb + (ch & 1) * WB_BUF;
#pragma unroll
                for (int ks = 0; ks < 2; ks++) {
                    int k0 = ch * 16 + ks * 8;
                    const float* ap = hbuf + (m0 + r0) * S_H + k0 + qk;
                    unsigned a[4];
                    a[0] = f2tf(ap[0]);
                    a[1] = f2tf(ap[8 * S_H]);
                    a[2] = f2tf(ap[4]);
                    a[3] = f2tf(ap[8 * S_H + 4]);
#pragma unroll
                    for (int nt = 0; nt < 8; nt++) {
                        const float* bp = cur + (ks * 8 + qk) * S_WA + n064 + 8 * nt + r0;
                        mma_tf32(acc2[nt], a, __float_as_uint(bp[0]),
                                 __float_as_uint(bp[4 * S_WA]));
                    }
                }
            }
            __syncthreads();  // all reads of tz (hf=0: none; safety) done; also
                              // ensures last wb reads done before GEMM3 issue

            // t_half -> tz (tf32-rounded bits, GEMM3 A operand)
#pragma unroll
            for (int nt = 0; nt < 8; nt++) {
                int col = n064 + 8 * nt + cb;
#pragma unroll
                for (int q = 0; q < 4; q++) {
                    int rr = m0 + r0 + (q >> 1) * 8;
                    int cc = col + (q & 1);
                    float t = fmaxf(acc2[nt][q] + __ldg(&b1[hf * 128 + cc]), 0.f);
                    tz[rr * S_H + cc] = __uint_as_float(f2tf(t));
                }
            }
        }
        __syncthreads();

        // ---- GEMM3 half: acc3 += t_half @ W2[hf*128:+128, :] ----
        {
            issue_w2h(hf, 0, 0);
            const int NCH = 4;
            for (int ch = 0; ch < NCH; ch++) {
                cp_wait<0>();
                __syncthreads();
                if (ch + 1 < NCH) issue_w2h(hf, ch + 1, (ch + 1) & 1);
                const float* cur = wb + (ch & 1) * WB_BUF;
#pragma unroll
                for (int ks = 0; ks < 4; ks++) {
                    int k0 = ch * 32 + ks * 8;
                    const float* ap = tz + (m0 + r0) * S_H + k0 + qk;
                    unsigned a[4];
                    a[0] = __float_as_uint(ap[0]);
                    a[1] = __float_as_uint(ap[8 * S_H]);
                    a[2] = __float_as_uint(ap[4]);
                    a[3] = __float_as_uint(ap[8 * S_H + 4]);
#pragma unroll
                    for (int nt = 0; nt < 8; nt++) {
                        const float* bp = cur + (ks * 8 + qk) * S_WA + n064 + 8 * nt + r0;
                        mma_tf32(acc3[nt], a, __float_as_uint(bp[0]),
                                 __float_as_uint(bp[4 * S_WA]));
                    }
                }
            }
        }
        __syncthreads();  // tz reads done before next hf overwrites it
    }

    // z = acc3 + b2 + h  -> tz (t-half dead)
#pragma unroll
    for (int nt = 0; nt < 8; nt++) {
        int col = n064 + 8 * nt + cb;
#pragma unroll
        for (int q = 0; q < 4; q++) {
            int rr = m0 + r0 + (q >> 1) * 8;
            int cc = col + (q & 1);
            tz[rr * S_H + cc] = acc3[nt][q] + __ldg(&b2[cc]) + hbuf[rr * S_H + cc];
        }
    }
    __syncthreads();

    // ---------------- LayerNorm2 -> global out ----------------
    for (int r = wid; r < TILE_E; r += 8) {
        int eg = e0 + r;
        float v[4], s = 0.f, s2 = 0.f;
#pragma unroll
        for (int q = 0; q < 4; q++) {
            v[q] = tz[r * S_H + lane + 32 * q];
            s += v[q];
            s2 += v[q] * v[q];
        }
#pragma unroll
        for (int off = 16; off > 0; off >>= 1) {
            s += __shfl_xor_sync(0xFFFFFFFF, s, off);
            s2 += __shfl_xor_sync(0xFFFFFFFF, s2, off);
        }
        float mu = s * (1.f / 128.f);
        float var = s2 * (1.f / 128.f) - mu * mu;
        float rinv = rsqrtf(var + EPS);
        if (eg < E) {
#pragma unroll
            for (int q = 0; q < 4; q++) {
                int c = lane + 32 * q;
                out[(size_t)eg * D_OUT + c] = (v[q] - mu) * rinv * __ldg(&g2[c]) + __ldg(&be2[c]);
            }
        }
    }
}

// ---------------------------------------------------------------------------
// launch
// ---------------------------------------------------------------------------
extern "C" void kernel_launch(void* const* d_in, const int* in_sizes, int n_in,
                              void* d_out, int out_size) {
    const void* p[16];
    int sz[16];
    int m = 0;
    for (int i = 0; i < n_in && m < 16; i++) {
        if (in_sizes[i] == 1) continue;
        p[m] = d_in[i];
        sz[m] = in_sizes[i];
        m++;
    }
    const float* x          = (const float*)p[0];
    const int*   edge_index = (const int*)p[1];
    const float* edge_attr  = (const float*)p[2];
    const float* mask       = (const float*)p[3];
    const float* We         = (const float*)p[4];
    const float* bE         = (const float*)p[5];
    const float* W1         = (const float*)p[6];
    const float* b1         = (const float*)p[7];
    const float* W2         = (const float*)p[8];
    const float* b2         = (const float*)p[9];
    const float* g1         = (const float*)p[10];
    const float* be1        = (const float*)p[11];
    const float* g2         = (const float*)p[12];
    const float* be2        = (const float*)p[13];

    const int N = sz[0] / 6;
    const int E = sz[3];

    float* out_node = (float*)d_out;                     // [N,134]
    float* out_edge = out_node + (size_t)N * D_NODEREP;  // [E,128]

    {
        int total = N * D_IN;
        zero_kernel<<<(total + 255) / 256, 256>>>(N);
    }
    {
        agg_kernel<<<(E + 7) / 8, 256>>>(edge_attr, mask, edge_index, E);
    }
    {
        const int smem = NP_SMEM_FLOATS * (int)sizeof(float);
        cudaFuncSetAttribute(nodeproj_kernel, cudaFuncAttributeMaxDynamicSharedMemorySize, smem);
        int blocks = (N + TILE_N - 1) / TILE_N;
        nodeproj_kernel<<<blocks, NPTHREADS, smem>>>(x, We, out_node, N);
    }
    {
        const int smem = E_SMEM_FLOATS * (int)sizeof(float);
        cudaFuncSetAttribute(edge_kernel, cudaFuncAttributeMaxDynamicSharedMemorySize, smem);
        int blocks = (E + TILE_E - 1) / TILE_E;
        edge_kernel<<<blocks, ETHREADS, smem>>>(edge_attr, edge_index,
                                                We, bE, W1, b1, W2, b2,
                                                g1, be1, g2, be2, out_edge, E);
    }
}